// round 1
// baseline (speedup 1.0000x reference)
#include <cuda_runtime.h>
#include <math.h>

// Problem constants (fixed shapes for this problem instance)
#define B  4
#define S  1024
#define H  768
#define NH 12
#define DH 64
#define PROX 512
#define NEGV (-100000.0f)
#define SCALE 0.125f   // 1/sqrt(64)

#define OUT_ELEMS   ((size_t)B * S * H)                 // 3,145,728
#define SCORES_ELEMS ((size_t)B * NH * S * S)           // 50,331,648
#define M_TOT (B * S)                                   // 4096

// ---------------------------------------------------------------------------
// Scratch (static device memory; no allocations allowed)
// ---------------------------------------------------------------------------
__device__ float g_hs [B * S * H];
__device__ float g_ctx[B * S * H];
__device__ float g_q  [B * S * H];
__device__ float g_k  [B * S * H];
__device__ float g_v  [B * S * H];
// Fallback scores buffer in case d_out only holds `out` (defensive)
__device__ float g_scores[B * NH * S * S];

// ---------------------------------------------------------------------------
// Kernel 1: hs = hidden + add, ctx = context + add   (add = vis where s<feat_len[b])
// ---------------------------------------------------------------------------
__global__ void add_kernel(const float* __restrict__ hidden,
                           const float* __restrict__ context,
                           const float* __restrict__ vis,
                           const int*   __restrict__ feat_len)
{
    size_t i4 = (size_t)blockIdx.x * blockDim.x + threadIdx.x;   // float4 index
    size_t base = i4 * 4;
    if (base >= OUT_ELEMS) return;
    int b = (int)(base / ((size_t)S * H));
    int s = (int)((base / H) % S);
    float4 h4 = ((const float4*)hidden)[i4];
    float4 c4 = ((const float4*)context)[i4];
    if (s < feat_len[b]) {
        float4 v4 = ((const float4*)vis)[i4];
        h4.x += v4.x; h4.y += v4.y; h4.z += v4.z; h4.w += v4.w;
        c4.x += v4.x; c4.y += v4.y; c4.z += v4.z; c4.w += v4.w;
    }
    ((float4*)g_hs)[i4]  = h4;
    ((float4*)g_ctx)[i4] = c4;
}

// ---------------------------------------------------------------------------
// Kernel 2: QKV projection.  Y[m,n] = sum_k X[m,k]*W[n,k] + bias[n]
// Classic fp32 SGEMM, 128x128 tile, BK=8, 256 threads, 8x8 per thread.
// grid = (768/128, 4096/128, 3)  z: 0->Q (X=hs), 1->K, 2->V (X=ctx)
// ---------------------------------------------------------------------------
__global__ void __launch_bounds__(256)
qkv_gemm(const float* __restrict__ Wq, const float* __restrict__ Wk,
         const float* __restrict__ Wv,
         const float* __restrict__ bq, const float* __restrict__ bk,
         const float* __restrict__ bv)
{
    const int z = blockIdx.z;
    const float* X    = (z == 0) ? g_hs : g_ctx;
    const float* W    = (z == 0) ? Wq : (z == 1 ? Wk : Wv);
    const float* bias = (z == 0) ? bq : (z == 1 ? bk : bv);
    float*       Y    = (z == 0) ? g_q : (z == 1 ? g_k : g_v);

    const int m0 = blockIdx.y * 128;
    const int n0 = blockIdx.x * 128;

    __shared__ float Xs[8][128];
    __shared__ float Ws[8][128];

    const int t    = threadIdx.x;
    const int lrow = t >> 1;          // 0..127
    const int lk4  = (t & 1) * 4;     // 0 or 4
    const int tx   = t & 15;
    const int ty   = t >> 4;

    float acc[8][8];
#pragma unroll
    for (int i = 0; i < 8; i++)
#pragma unroll
        for (int j = 0; j < 8; j++) acc[i][j] = 0.f;

    const float* xptr = X + (size_t)(m0 + lrow) * H + lk4;
    const float* wptr = W + (size_t)(n0 + lrow) * H + lk4;

    for (int k0 = 0; k0 < H; k0 += 8) {
        float4 xa = *(const float4*)(xptr + k0);
        float4 wa = *(const float4*)(wptr + k0);
        Xs[lk4 + 0][lrow] = xa.x; Xs[lk4 + 1][lrow] = xa.y;
        Xs[lk4 + 2][lrow] = xa.z; Xs[lk4 + 3][lrow] = xa.w;
        Ws[lk4 + 0][lrow] = wa.x; Ws[lk4 + 1][lrow] = wa.y;
        Ws[lk4 + 2][lrow] = wa.z; Ws[lk4 + 3][lrow] = wa.w;
        __syncthreads();
#pragma unroll
        for (int kk = 0; kk < 8; kk++) {
            float4 a0 = *(const float4*)&Xs[kk][ty * 8];
            float4 a1 = *(const float4*)&Xs[kk][ty * 8 + 4];
            float4 b0 = *(const float4*)&Ws[kk][tx * 8];
            float4 b1 = *(const float4*)&Ws[kk][tx * 8 + 4];
            float av[8] = {a0.x, a0.y, a0.z, a0.w, a1.x, a1.y, a1.z, a1.w};
            float bv2[8] = {b0.x, b0.y, b0.z, b0.w, b1.x, b1.y, b1.z, b1.w};
#pragma unroll
            for (int i = 0; i < 8; i++)
#pragma unroll
                for (int j = 0; j < 8; j++) acc[i][j] += av[i] * bv2[j];
        }
        __syncthreads();
    }

#pragma unroll
    for (int i = 0; i < 8; i++) {
        int m = m0 + ty * 8 + i;
        float* yr = Y + (size_t)m * H + n0 + tx * 8;
        const float* br = bias + n0 + tx * 8;
        float4 o0, o1;
        o0.x = acc[i][0] + br[0]; o0.y = acc[i][1] + br[1];
        o0.z = acc[i][2] + br[2]; o0.w = acc[i][3] + br[3];
        o1.x = acc[i][4] + br[4]; o1.y = acc[i][5] + br[5];
        o1.z = acc[i][6] + br[6]; o1.w = acc[i][7] + br[7];
        *(float4*)yr       = o0;
        *(float4*)(yr + 4) = o1;
    }
}

// ---------------------------------------------------------------------------
// Kernel 3a: band rows (r in [0, PROX-1)).  Fill row with NEG, set cols {r-1, r}.
// grid = (PROX-1, B*NH), 256 threads
// ---------------------------------------------------------------------------
__global__ void band_scores(const float* __restrict__ gate,
                            const float* __restrict__ am,
                            float* __restrict__ scores)
{
    const int r  = blockIdx.x;           // 0..510
    const int bh = blockIdx.y;
    const int b = bh / NH, h = bh % NH;
    float* srow = scores + ((size_t)bh * S + r) * S;
    const int t = threadIdx.x;

    float4 neg4 = make_float4(NEGV, NEGV, NEGV, NEGV);
    ((float4*)srow)[t] = neg4;
    __syncthreads();

    const int w = t >> 5, lane = t & 31;
    if (w < 2) {
        int c = r - w;
        if (c >= 0) {
            const float* qr = g_q + ((size_t)b * S + r) * H + h * DH;
            const float* kr = g_k + ((size_t)b * S + c) * H + h * DH;
            float p = qr[lane] * kr[lane] + qr[lane + 32] * kr[lane + 32];
#pragma unroll
            for (int o = 16; o; o >>= 1) p += __shfl_xor_sync(0xffffffffu, p, o);
            if (lane == 0)
                srow[c] = p * SCALE * gate[((size_t)b * S + r) * S + c] + am[(size_t)b * S + c];
        }
    }
}

// ---------------------------------------------------------------------------
// Kernel 3b: full row r = PROX-1.  grid = (B*NH), 256 threads.
// ---------------------------------------------------------------------------
__global__ void fullrow_scores(const float* __restrict__ gate,
                               const float* __restrict__ am,
                               float* __restrict__ scores)
{
    const int bh = blockIdx.x;
    const int b = bh / NH, h = bh % NH;
    const int r = PROX - 1;
    __shared__ float qs[DH];
    const int t = threadIdx.x;
    if (t < DH) qs[t] = g_q[((size_t)b * S + r) * H + h * DH + t];
    __syncthreads();
    float* srow = scores + ((size_t)bh * S + r) * S;
    for (int c = t; c < S; c += 256) {
        const float4* k4 = (const float4*)(g_k + ((size_t)b * S + c) * H + h * DH);
        float acc = 0.f;
#pragma unroll
        for (int d4 = 0; d4 < 16; d4++) {
            float4 kv = k4[d4];
            acc += qs[d4 * 4 + 0] * kv.x + qs[d4 * 4 + 1] * kv.y
                 + qs[d4 * 4 + 2] * kv.z + qs[d4 * 4 + 3] * kv.w;
        }
        srow[c] = acc * SCALE * gate[((size_t)b * S + r) * S + c] + am[(size_t)b * S + c];
    }
}

// ---------------------------------------------------------------------------
// Kernel 3c: rows [PROX, S).  64x64 tiles; compute where cols in [lo, PROX),
// NEG elsewhere.  grid = (S/64, (S-PROX)/64, B*NH), 256 threads.
// ---------------------------------------------------------------------------
__global__ void __launch_bounds__(256)
block_scores(const float* __restrict__ gate,
             const float* __restrict__ am,
             const int*   __restrict__ feat_len,
             float* __restrict__ scores)
{
    const int bh = blockIdx.z;
    const int b = bh / NH, h = bh % NH;
    const int r0 = PROX + blockIdx.y * 64;
    const int c0 = blockIdx.x * 64;
    const int fl = feat_len[b];
    const int lo = max(fl - 1, 0);
    const int t = threadIdx.x;
    float* sbase = scores + ((size_t)bh * S + r0) * S;

    if (c0 >= PROX || c0 + 64 <= lo) {
        float4 neg4 = make_float4(NEGV, NEGV, NEGV, NEGV);
#pragma unroll
        for (int i = 0; i < 4; i++) {
            int idx = t + i * 256;           // float4 units over 64x64
            int row = idx >> 4, col4 = idx & 15;
            *(float4*)(sbase + (size_t)row * S + c0 + col4 * 4) = neg4;
        }
        return;
    }

    __shared__ float Qs[64][65];
    __shared__ float Ks[64][65];
#pragma unroll
    for (int i = 0; i < 4; i++) {
        int idx = t + i * 256;
        int row = idx >> 4, f4 = idx & 15;
        float4 qv = *(const float4*)(g_q + ((size_t)(b * S + r0 + row)) * H + h * DH + f4 * 4);
        float4 kv = *(const float4*)(g_k + ((size_t)(b * S + c0 + row)) * H + h * DH + f4 * 4);
        Qs[row][f4 * 4 + 0] = qv.x; Qs[row][f4 * 4 + 1] = qv.y;
        Qs[row][f4 * 4 + 2] = qv.z; Qs[row][f4 * 4 + 3] = qv.w;
        Ks[row][f4 * 4 + 0] = kv.x; Ks[row][f4 * 4 + 1] = kv.y;
        Ks[row][f4 * 4 + 2] = kv.z; Ks[row][f4 * 4 + 3] = kv.w;
    }
    __syncthreads();

    const int tx = t & 15, ty = t >> 4;
    float acc[4][4];
#pragma unroll
    for (int i = 0; i < 4; i++)
#pragma unroll
        for (int j = 0; j < 4; j++) acc[i][j] = 0.f;

#pragma unroll 8
    for (int kk = 0; kk < 64; kk++) {
        float a[4], bb[4];
#pragma unroll
        for (int i = 0; i < 4; i++) a[i] = Qs[ty * 4 + i][kk];
#pragma unroll
        for (int j = 0; j < 4; j++) bb[j] = Ks[tx * 4 + j][kk];
#pragma unroll
        for (int i = 0; i < 4; i++)
#pragma unroll
            for (int j = 0; j < 4; j++) acc[i][j] += a[i] * bb[j];
    }

#pragma unroll
    for (int i = 0; i < 4; i++) {
        int rr = ty * 4 + i;
        int r = r0 + rr;
#pragma unroll
        for (int j = 0; j < 4; j++) {
            int c = c0 + tx * 4 + j;
            bool un = (c >= lo) && (c < PROX);
            float val = un
                ? acc[i][j] * SCALE * gate[((size_t)b * S + r) * S + c] + am[(size_t)b * S + c]
                : NEGV;
            sbase[(size_t)rr * S + c] = val;
        }
    }
}

// ---------------------------------------------------------------------------
// Kernel 4a: out rows [0, PROX).  grid = (PROX, B*NH), 64 threads.
// ---------------------------------------------------------------------------
__global__ void out_top(const float* __restrict__ scores, float* __restrict__ out)
{
    const int r  = blockIdx.x;
    const int bh = blockIdx.y;
    const int b = bh / NH, h = bh % NH;
    const int d = threadIdx.x;      // 0..63
    const float* srow = scores + ((size_t)bh * S + r) * S;
    const float* vb   = g_v + (size_t)b * S * H + h * DH;
    float* orow       = out + ((size_t)b * S + r) * H + h * DH;

    __shared__ float pr[S];
    __shared__ float red[2];

    if (r < PROX - 1) {
        float s1 = srow[r];
        float s0 = (r > 0) ? srow[r - 1] : -1e30f;
        float m = fmaxf(s0, s1);
        float e0 = expf(s0 - m), e1 = expf(s1 - m);
        float Z = e0 + e1;
        float val = e1 * vb[(size_t)r * H + d];
        if (r > 0) val += e0 * vb[(size_t)(r - 1) * H + d];
        orow[d] = val / Z;
    } else {
        // full softmax over 1024
        float m = -1e30f;
        for (int c = d; c < S; c += 64) m = fmaxf(m, srow[c]);
#pragma unroll
        for (int o = 16; o; o >>= 1) m = fmaxf(m, __shfl_xor_sync(0xffffffffu, m, o));
        if ((d & 31) == 0) red[d >> 5] = m;
        __syncthreads();
        m = fmaxf(red[0], red[1]);
        __syncthreads();
        float z = 0.f;
        for (int c = d; c < S; c += 64) { float e = expf(srow[c] - m); pr[c] = e; z += e; }
#pragma unroll
        for (int o = 16; o; o >>= 1) z += __shfl_xor_sync(0xffffffffu, z, o);
        if ((d & 31) == 0) red[d >> 5] = z;
        __syncthreads();
        float Z = red[0] + red[1];
        float acc = 0.f;
        for (int c = 0; c < S; c++) acc += pr[c] * vb[(size_t)c * H + d];
        orow[d] = acc / Z;
    }
}

// ---------------------------------------------------------------------------
// Kernel 4b: out rows [PROX, S).  grid = ((S-PROX)/16, B*NH), 256 threads.
// ---------------------------------------------------------------------------
__global__ void __launch_bounds__(256)
out_bottom(const float* __restrict__ scores, const int* __restrict__ feat_len,
           float* __restrict__ out)
{
    const int bh = blockIdx.y;
    const int b = bh / NH, h = bh % NH;
    const int r0 = PROX + blockIdx.x * 16;
    const int fl = feat_len[b];
    const int t = threadIdx.x;
    const float* vb = g_v + (size_t)b * S * H + h * DH;
    float* ob = out + ((size_t)b * S + r0) * H + h * DH;

    __shared__ float probs[16][512];
    __shared__ float zrow[16];
    __shared__ float red[4][64];

    if (fl >= PROX + 1) {
        // fully masked rows -> uniform over all S
        int d = t & 63, qd = t >> 6;   // 4 quarters
        float acc = 0.f;
        for (int c = qd * 256; c < qd * 256 + 256; ++c) acc += vb[(size_t)c * H + d];
        red[qd][d] = acc;
        __syncthreads();
        if (t < 64) {
            float tot = (red[0][t] + red[1][t] + red[2][t] + red[3][t]) * (1.0f / (float)S);
            for (int row = 0; row < 16; ++row) ob[(size_t)row * H + t] = tot;
        }
        return;
    }

    const int lo = max(fl - 1, 0);     // <= 511 here
    const int row = t >> 4, lane = t & 15;
    const int r = r0 + row;
    const float* srow = scores + ((size_t)bh * S + r) * S;

    float m = -1e30f;
    for (int c = lo + lane; c < PROX; c += 16) m = fmaxf(m, srow[c]);
#pragma unroll
    for (int o = 8; o; o >>= 1) m = fmaxf(m, __shfl_xor_sync(0xffffffffu, m, o));
    float z = 0.f;
    for (int c = lo + lane; c < PROX; c += 16) {
        float e = expf(srow[c] - m);
        probs[row][c - lo] = e;
        z += e;
    }
#pragma unroll
    for (int o = 8; o; o >>= 1) z += __shfl_xor_sync(0xffffffffu, z, o);
    if (lane == 0) zrow[row] = z;
    __syncthreads();

    // accumulation: thread = (row, 4-dim chunk)
    const int arow = t >> 4;
    const int d = (t & 15) * 4;
    float4 acc = make_float4(0.f, 0.f, 0.f, 0.f);
    for (int c = lo; c < PROX; c++) {
        float p = probs[arow][c - lo];
        float4 v4 = *(const float4*)(vb + (size_t)c * H + d);
        acc.x += p * v4.x; acc.y += p * v4.y; acc.z += p * v4.z; acc.w += p * v4.w;
    }
    float invZ = 1.f / zrow[arow];
    float4 o4 = make_float4(acc.x * invZ, acc.y * invZ, acc.z * invZ, acc.w * invZ);
    *(float4*)(ob + (size_t)arow * H + d) = o4;
}

// ---------------------------------------------------------------------------
// Launch
// ---------------------------------------------------------------------------
extern "C" void kernel_launch(void* const* d_in, const int* in_sizes, int n_in,
                              void* d_out, int out_size)
{
    const float* hidden  = (const float*)d_in[0];
    const float* context = (const float*)d_in[1];
    const float* am      = (const float*)d_in[2];
    const float* gate    = (const float*)d_in[3];
    const float* vis     = (const float*)d_in[4];
    const float* Wq      = (const float*)d_in[5];
    const float* bq      = (const float*)d_in[6];
    const float* Wk      = (const float*)d_in[7];
    const float* bk      = (const float*)d_in[8];
    const float* Wv      = (const float*)d_in[9];
    const float* bv      = (const float*)d_in[10];
    const int*   feat    = (const int*)d_in[11];

    float* outp = (float*)d_out;
    float* scores;
    if ((size_t)out_size >= OUT_ELEMS + SCORES_ELEMS) {
        scores = outp + OUT_ELEMS;           // tuple (out, scores) flattened
    } else {
        void* p = nullptr;
        cudaGetSymbolAddress(&p, g_scores);
        scores = (float*)p;
    }

    // 1. positional add
    add_kernel<<<(unsigned)(OUT_ELEMS / 4 / 256), 256>>>(hidden, context, vis, feat);

    // 2. QKV GEMMs
    {
        dim3 grid(H / 128, M_TOT / 128, 3);
        qkv_gemm<<<grid, 256>>>(Wq, Wk, Wv, bq, bk, bv);
    }

    // 3. scores
    {
        dim3 gb(PROX - 1, B * NH);
        band_scores<<<gb, 256>>>(gate, am, scores);
        fullrow_scores<<<B * NH, 256>>>(gate, am, scores);
        dim3 gc(S / 64, (S - PROX) / 64, B * NH);
        block_scores<<<gc, 256>>>(gate, am, feat, scores);
    }

    // 4. softmax + PV -> out
    {
        dim3 gt(PROX, B * NH);
        out_top<<<gt, 64>>>(scores, outp);
        dim3 gbm((S - PROX) / 16, B * NH);
        out_bottom<<<gbm, 256>>>(scores, feat, outp);
    }

    (void)in_sizes; (void)n_in;
}

// round 3
// speedup vs baseline: 1.4210x; 1.4210x over previous
#include <cuda_runtime.h>
#include <cuda_bf16.h>
#include <math.h>
#include <stdint.h>

// Problem constants
#define B  4
#define S  1024
#define H  768
#define NH 12
#define DH 64
#define PROX 512
#define NEGV (-100000.0f)
#define SCALE 0.125f

#define OUT_ELEMS    ((size_t)B * S * H)        // 3,145,728
#define SCORES_ELEMS ((size_t)B * NH * S * S)   // 50,331,648
#define M_TOT (B * S)                           // 4096

// ---------------------------------------------------------------------------
// Static device scratch
// ---------------------------------------------------------------------------
__device__ __nv_bfloat16 g_hs_hi [M_TOT * H];
__device__ __nv_bfloat16 g_hs_lo [M_TOT * H];
__device__ __nv_bfloat16 g_ctx_hi[M_TOT * H];
__device__ __nv_bfloat16 g_ctx_lo[M_TOT * H];
__device__ __nv_bfloat16 g_w_hi[3 * H * H];
__device__ __nv_bfloat16 g_w_lo[3 * H * H];
__device__ float g_q[M_TOT * H];
__device__ float g_k[M_TOT * H];
__device__ float g_v[M_TOT * H];
__device__ float g_scores_fb[B * NH * S * S];   // fallback only

// ---------------------------------------------------------------------------
// PTX helpers (sm_100 baseline: cp.async + ldmatrix + mma.sync)
// ---------------------------------------------------------------------------
__device__ __forceinline__ uint32_t smem_u32(const void* p) {
    uint32_t a;
    asm("{ .reg .u64 t; cvta.to.shared.u64 t, %1; cvt.u32.u64 %0, t; }" : "=r"(a) : "l"(p));
    return a;
}
#define CP_ASYNC16(saddr, gptr) \
    asm volatile("cp.async.cg.shared.global [%0], [%1], 16;" :: "r"(saddr), "l"(gptr))
#define CP_COMMIT  asm volatile("cp.async.commit_group;" ::: "memory")
#define CP_WAIT1   asm volatile("cp.async.wait_group 1;" ::: "memory")
#define CP_WAIT0   asm volatile("cp.async.wait_group 0;" ::: "memory")

__device__ __forceinline__ void ldsm_x4(uint32_t& r0, uint32_t& r1, uint32_t& r2,
                                        uint32_t& r3, uint32_t addr) {
    asm volatile("ldmatrix.sync.aligned.m8n8.x4.shared.b16 {%0,%1,%2,%3}, [%4];"
                 : "=r"(r0), "=r"(r1), "=r"(r2), "=r"(r3) : "r"(addr));
}
__device__ __forceinline__ void mma_bf16(float* d, uint32_t a0, uint32_t a1,
                                         uint32_t a2, uint32_t a3,
                                         uint32_t b0, uint32_t b1) {
    asm volatile(
        "mma.sync.aligned.m16n8k16.row.col.f32.bf16.bf16.f32 "
        "{%0,%1,%2,%3}, {%4,%5,%6,%7}, {%8,%9}, {%0,%1,%2,%3};"
        : "+f"(d[0]), "+f"(d[1]), "+f"(d[2]), "+f"(d[3])
        : "r"(a0), "r"(a1), "r"(a2), "r"(a3), "r"(b0), "r"(b1));
}

// ---------------------------------------------------------------------------
// Kernel 1: positional add + bf16 hi/lo split
// ---------------------------------------------------------------------------
struct bf4 { __nv_bfloat16 v[4]; };

__global__ void add_prep(const float* __restrict__ hidden,
                         const float* __restrict__ context,
                         const float* __restrict__ vis,
                         const int*   __restrict__ feat_len)
{
    size_t i4 = (size_t)blockIdx.x * blockDim.x + threadIdx.x;
    size_t base = i4 * 4;
    if (base >= OUT_ELEMS) return;
    int b = (int)(base / ((size_t)S * H));
    int s = (int)((base / H) % S);
    float4 h4 = ((const float4*)hidden)[i4];
    float4 c4 = ((const float4*)context)[i4];
    if (s < feat_len[b]) {
        float4 v4 = ((const float4*)vis)[i4];
        h4.x += v4.x; h4.y += v4.y; h4.z += v4.z; h4.w += v4.w;
        c4.x += v4.x; c4.y += v4.y; c4.z += v4.z; c4.w += v4.w;
    }
    float hv[4] = {h4.x, h4.y, h4.z, h4.w};
    float cv[4] = {c4.x, c4.y, c4.z, c4.w};
    bf4 hh, hl, ch, cl;
#pragma unroll
    for (int j = 0; j < 4; j++) {
        __nv_bfloat16 a = __float2bfloat16(hv[j]);
        hh.v[j] = a; hl.v[j] = __float2bfloat16(hv[j] - __bfloat162float(a));
        __nv_bfloat16 d = __float2bfloat16(cv[j]);
        ch.v[j] = d; cl.v[j] = __float2bfloat16(cv[j] - __bfloat162float(d));
    }
    ((bf4*)g_hs_hi)[i4]  = hh; ((bf4*)g_hs_lo)[i4]  = hl;
    ((bf4*)g_ctx_hi)[i4] = ch; ((bf4*)g_ctx_lo)[i4] = cl;
}

// ---------------------------------------------------------------------------
// Kernel 2: weight hi/lo split (z = 0,1,2 -> Wq,Wk,Wv)
// ---------------------------------------------------------------------------
__global__ void prep_w(const float* __restrict__ Wq, const float* __restrict__ Wk,
                       const float* __restrict__ Wv)
{
    const int z = blockIdx.y;
    const float* W = (z == 0) ? Wq : (z == 1) ? Wk : Wv;
    size_t i4 = (size_t)blockIdx.x * blockDim.x + threadIdx.x;
    if (i4 >= (size_t)H * H / 4) return;
    float4 w4 = ((const float4*)W)[i4];
    float wv[4] = {w4.x, w4.y, w4.z, w4.w};
    bf4 hi, lo;
#pragma unroll
    for (int j = 0; j < 4; j++) {
        __nv_bfloat16 a = __float2bfloat16(wv[j]);
        hi.v[j] = a; lo.v[j] = __float2bfloat16(wv[j] - __bfloat162float(a));
    }
    ((bf4*)(g_w_hi + (size_t)z * H * H))[i4] = hi;
    ((bf4*)(g_w_lo + (size_t)z * H * H))[i4] = lo;
}

// ---------------------------------------------------------------------------
// Kernel 3: QKV via mma.sync bf16 split GEMM.
// Y[m,n] = sum_k X[m,k] W[n,k] + bias, K' = 2304 (hi*hi + lo*hi + hi*lo)
// BM=128, BN=128, BK=32, 8 warps (4 along M x 2 along N), warp tile 32x64.
// grid = (768/128, 4096/128, 3), 256 threads.
// ---------------------------------------------------------------------------
#define BKq 32
#define NROUNDS (3 * H / BKq)   // 72
#define SROW 80                 // smem row pitch (bytes): conflict-free ldmatrix
#define STILE (128 * SROW)      // 10240 bytes per tile buffer

__global__ void __launch_bounds__(256)
qkv_mma(const float* __restrict__ bq, const float* __restrict__ bk,
        const float* __restrict__ bv)
{
    __shared__ char smA[2 * STILE];
    __shared__ char smB[2 * STILE];

    const int z = blockIdx.z;
    const __nv_bfloat16* Ahi = (z == 0) ? g_hs_hi : g_ctx_hi;
    const __nv_bfloat16* Alo = (z == 0) ? g_hs_lo : g_ctx_lo;
    const __nv_bfloat16* Whi = g_w_hi + (size_t)z * H * H;
    const __nv_bfloat16* Wlo = g_w_lo + (size_t)z * H * H;
    const float* bias = (z == 0) ? bq : (z == 1) ? bk : bv;
    float* Y = (z == 0) ? g_q : (z == 1) ? g_k : g_v;

    const int m0 = blockIdx.y * 128;
    const int n0 = blockIdx.x * 128;
    const int tid = threadIdx.x;
    const int lane = tid & 31;
    const int wid = tid >> 5;
    const int warp_m = wid & 3;     // 0..3 -> 32-row slices
    const int warp_n = wid >> 2;    // 0..1 -> 64-col slices

    const uint32_t sA = smem_u32(smA);
    const uint32_t sB = smem_u32(smB);

    const int ldrow = tid >> 2;          // 0..63  (x2 iters -> 128 rows)
    const int ldch  = tid & 3;           // 16B chunk

    float acc[2][8][4];
#pragma unroll
    for (int i = 0; i < 2; i++)
#pragma unroll
        for (int j = 0; j < 8; j++)
#pragma unroll
            for (int q = 0; q < 4; q++) acc[i][j][q] = 0.f;

    // ---- stage loader ----
    auto load_stage = [&](int r, int buf) {
        const int kp = r * BKq;
        const int phase = kp / H;
        const int k0 = kp % H;
        const __nv_bfloat16* As = (phase == 1) ? Alo : Ahi;
        const __nv_bfloat16* Bs = (phase == 2) ? Wlo : Whi;
        const uint32_t a_s = sA + buf * STILE;
        const uint32_t b_s = sB + buf * STILE;
#pragma unroll
        for (int i = 0; i < 2; i++) {
            int row = ldrow + i * 64;
            CP_ASYNC16(a_s + row * SROW + ldch * 16,
                       As + (size_t)(m0 + row) * H + k0 + ldch * 8);
        }
#pragma unroll
        for (int i = 0; i < 2; i++) {
            int row = ldrow + i * 64;
            CP_ASYNC16(b_s + row * SROW + ldch * 16,
                       Bs + (size_t)(n0 + row) * H + k0 + ldch * 8);
        }
        CP_COMMIT;
    };

    load_stage(0, 0);

    const uint32_t aBase = sA + (warp_m * 32 + (lane & 15)) * SROW + (lane >> 4) * 16;
    const uint32_t bBase = sB + (warp_n * 64 + ((lane >> 4) << 3) + (lane & 7)) * SROW
                         + ((lane >> 3) & 1) * 16;

    for (int r = 0; r < NROUNDS; r++) {
        const int buf = r & 1;
        if (r + 1 < NROUNDS) { load_stage(r + 1, buf ^ 1); CP_WAIT1; }
        else                 { CP_WAIT0; }
        __syncthreads();

#pragma unroll
        for (int kk = 0; kk < 2; kk++) {
            uint32_t a[2][4];
#pragma unroll
            for (int mt = 0; mt < 2; mt++)
                ldsm_x4(a[mt][0], a[mt][1], a[mt][2], a[mt][3],
                        aBase + buf * STILE + mt * 16 * SROW + kk * 32);
            uint32_t bfr[8][2];
#pragma unroll
            for (int nt2 = 0; nt2 < 4; nt2++) {
                uint32_t r0, r1, r2, r3;
                ldsm_x4(r0, r1, r2, r3,
                        bBase + buf * STILE + nt2 * 16 * SROW + kk * 32);
                bfr[nt2 * 2][0] = r0; bfr[nt2 * 2][1] = r1;
                bfr[nt2 * 2 + 1][0] = r2; bfr[nt2 * 2 + 1][1] = r3;
            }
#pragma unroll
            for (int mt = 0; mt < 2; mt++)
#pragma unroll
                for (int nt = 0; nt < 8; nt++)
                    mma_bf16(acc[mt][nt], a[mt][0], a[mt][1], a[mt][2], a[mt][3],
                             bfr[nt][0], bfr[nt][1]);
        }
        __syncthreads();
    }

    // ---- epilogue: direct global stores + bias ----
#pragma unroll
    for (int mt = 0; mt < 2; mt++) {
        int mbase = m0 + warp_m * 32 + mt * 16 + (lane >> 2);
#pragma unroll
        for (int nt = 0; nt < 8; nt++) {
            int n = n0 + warp_n * 64 + nt * 8 + (lane & 3) * 2;
            float b0 = bias[n], b1 = bias[n + 1];
            float2 v0 = make_float2(acc[mt][nt][0] + b0, acc[mt][nt][1] + b1);
            float2 v1 = make_float2(acc[mt][nt][2] + b0, acc[mt][nt][3] + b1);
            *(float2*)(Y + (size_t)mbase * H + n) = v0;
            *(float2*)(Y + (size_t)(mbase + 8) * H + n) = v1;
        }
    }
}

// ---------------------------------------------------------------------------
// Kernel 4a: band rows (r in [0, PROX-1)) — NEG fill + 2 dots
// ---------------------------------------------------------------------------
__global__ void band_scores(const float* __restrict__ gate,
                            const float* __restrict__ am,
                            float* __restrict__ scores)
{
    const int r  = blockIdx.x;
    const int bh = blockIdx.y;
    const int b = bh / NH, h = bh % NH;
    float* srow = scores + ((size_t)bh * S + r) * S;
    const int t = threadIdx.x;

    float4 neg4 = make_float4(NEGV, NEGV, NEGV, NEGV);
    ((float4*)srow)[t] = neg4;
    __syncthreads();

    const int w = t >> 5, lane = t & 31;
    if (w < 2) {
        int c = r - w;
        if (c >= 0) {
            const float* qr = g_q + ((size_t)b * S + r) * H + h * DH;
            const float* kr = g_k + ((size_t)b * S + c) * H + h * DH;
            float p = qr[lane] * kr[lane] + qr[lane + 32] * kr[lane + 32];
#pragma unroll
            for (int o = 16; o; o >>= 1) p += __shfl_xor_sync(0xffffffffu, p, o);
            if (lane == 0)
                srow[c] = p * SCALE * gate[((size_t)b * S + r) * S + c] + am[(size_t)b * S + c];
        }
    }
}

// ---------------------------------------------------------------------------
// Kernel 4b: full row r = PROX-1.  grid = (B*NH, 4), 256 threads.
// ---------------------------------------------------------------------------
__global__ void fullrow_scores(const float* __restrict__ gate,
                               const float* __restrict__ am,
                               float* __restrict__ scores)
{
    const int bh = blockIdx.x;
    const int b = bh / NH, h = bh % NH;
    const int r = PROX - 1;
    __shared__ float qs[DH];
    const int t = threadIdx.x;
    if (t < DH) qs[t] = g_q[((size_t)b * S + r) * H + h * DH + t];
    __syncthreads();
    float* srow = scores + ((size_t)bh * S + r) * S;
    int c = blockIdx.y * 256 + t;
    const float4* k4 = (const float4*)(g_k + ((size_t)b * S + c) * H + h * DH);
    float acc = 0.f;
#pragma unroll
    for (int d4 = 0; d4 < 16; d4++) {
        float4 kv = k4[d4];
        acc += qs[d4 * 4 + 0] * kv.x + qs[d4 * 4 + 1] * kv.y
             + qs[d4 * 4 + 2] * kv.z + qs[d4 * 4 + 3] * kv.w;
    }
    srow[c] = acc * SCALE * gate[((size_t)b * S + r) * S + c] + am[(size_t)b * S + c];
}

// ---------------------------------------------------------------------------
// Kernel 4c: rows [PROX, S) — 64x64 tiles, compute [lo,PROX), NEG elsewhere
// ---------------------------------------------------------------------------
__global__ void __launch_bounds__(256)
block_scores(const float* __restrict__ gate,
             const float* __restrict__ am,
             const int*   __restrict__ feat_len,
             float* __restrict__ scores)
{
    const int bh = blockIdx.z;
    const int b = bh / NH, h = bh % NH;
    const int r0 = PROX + blockIdx.y * 64;
    const int c0 = blockIdx.x * 64;
    const int fl = feat_len[b];
    const int lo = max(fl - 1, 0);
    const int t = threadIdx.x;
    float* sbase = scores + ((size_t)bh * S + r0) * S;

    if (c0 >= PROX || c0 + 64 <= lo) {
        float4 neg4 = make_float4(NEGV, NEGV, NEGV, NEGV);
#pragma unroll
        for (int i = 0; i < 4; i++) {
            int idx = t + i * 256;
            int row = idx >> 4, col4 = idx & 15;
            *(float4*)(sbase + (size_t)row * S + c0 + col4 * 4) = neg4;
        }
        return;
    }

    __shared__ float Qs[64][65];
    __shared__ float Ks[64][65];
#pragma unroll
    for (int i = 0; i < 4; i++) {
        int idx = t + i * 256;
        int row = idx >> 4, f4 = idx & 15;
        float4 qv = *(const float4*)(g_q + ((size_t)(b * S + r0 + row)) * H + h * DH + f4 * 4);
        float4 kv = *(const float4*)(g_k + ((size_t)(b * S + c0 + row)) * H + h * DH + f4 * 4);
        Qs[row][f4 * 4 + 0] = qv.x; Qs[row][f4 * 4 + 1] = qv.y;
        Qs[row][f4 * 4 + 2] = qv.z; Qs[row][f4 * 4 + 3] = qv.w;
        Ks[row][f4 * 4 + 0] = kv.x; Ks[row][f4 * 4 + 1] = kv.y;
        Ks[row][f4 * 4 + 2] = kv.z; Ks[row][f4 * 4 + 3] = kv.w;
    }
    __syncthreads();

    const int tx = t & 15, ty = t >> 4;
    float acc[4][4];
#pragma unroll
    for (int i = 0; i < 4; i++)
#pragma unroll
        for (int j = 0; j < 4; j++) acc[i][j] = 0.f;

#pragma unroll 8
    for (int kk = 0; kk < 64; kk++) {
        float a[4], bb[4];
#pragma unroll
        for (int i = 0; i < 4; i++) a[i] = Qs[ty * 4 + i][kk];
#pragma unroll
        for (int j = 0; j < 4; j++) bb[j] = Ks[tx * 4 + j][kk];
#pragma unroll
        for (int i = 0; i < 4; i++)
#pragma unroll
            for (int j = 0; j < 4; j++) acc[i][j] += a[i] * bb[j];
    }

#pragma unroll
    for (int i = 0; i < 4; i++) {
        int rr = ty * 4 + i;
        int r = r0 + rr;
#pragma unroll
        for (int j = 0; j < 4; j++) {
            int c = c0 + tx * 4 + j;
            bool un = (c >= lo) && (c < PROX);
            float val = un
                ? acc[i][j] * SCALE * gate[((size_t)b * S + r) * S + c] + am[(size_t)b * S + c]
                : NEGV;
            sbase[(size_t)rr * S + c] = val;
        }
    }
}

// ---------------------------------------------------------------------------
// Kernel 5a: out rows [0, PROX)
// ---------------------------------------------------------------------------
__global__ void out_top(const float* __restrict__ scores, float* __restrict__ out)
{
    const int r  = blockIdx.x;
    const int bh = blockIdx.y;
    const int b = bh / NH, h = bh % NH;
    const int d = threadIdx.x;
    const float* srow = scores + ((size_t)bh * S + r) * S;
    const float* vb   = g_v + (size_t)b * S * H + h * DH;
    float* orow       = out + ((size_t)b * S + r) * H + h * DH;

    __shared__ float pr[S];
    __shared__ float red[2];

    if (r < PROX - 1) {
        float s1 = srow[r];
        float s0 = (r > 0) ? srow[r - 1] : -1e30f;
        float m = fmaxf(s0, s1);
        float e0 = expf(s0 - m), e1 = expf(s1 - m);
        float Z = e0 + e1;
        float val = e1 * vb[(size_t)r * H + d];
        if (r > 0) val += e0 * vb[(size_t)(r - 1) * H + d];
        orow[d] = val / Z;
    } else {
        float m = -1e30f;
        for (int c = d; c < S; c += 64) m = fmaxf(m, srow[c]);
#pragma unroll
        for (int o = 16; o; o >>= 1) m = fmaxf(m, __shfl_xor_sync(0xffffffffu, m, o));
        if ((d & 31) == 0) red[d >> 5] = m;
        __syncthreads();
        m = fmaxf(red[0], red[1]);
        __syncthreads();
        float z = 0.f;
        for (int c = d; c < S; c += 64) { float e = expf(srow[c] - m); pr[c] = e; z += e; }
#pragma unroll
        for (int o = 16; o; o >>= 1) z += __shfl_xor_sync(0xffffffffu, z, o);
        if ((d & 31) == 0) red[d >> 5] = z;
        __syncthreads();
        float Z = red[0] + red[1];
        float acc = 0.f;
        for (int c = 0; c < S; c++) acc += pr[c] * vb[(size_t)c * H + d];
        orow[d] = acc / Z;
    }
}

// ---------------------------------------------------------------------------
// Kernel 5b: out rows [PROX, S) — transposed probs, 16-row register reuse.
// grid = ((S-PROX)/16, B*NH), 256 threads.
// ---------------------------------------------------------------------------
__global__ void __launch_bounds__(256)
out_bottom(const float* __restrict__ scores, const int* __restrict__ feat_len,
           float* __restrict__ out)
{
    const int bh = blockIdx.y;
    const int b = bh / NH, h = bh % NH;
    const int r0 = PROX + blockIdx.x * 16;
    const int fl = feat_len[b];
    const int t = threadIdx.x;
    const float* vb = g_v + (size_t)b * S * H + h * DH;
    float* ob = out + ((size_t)b * S + r0) * H + h * DH;

    __shared__ float pt[512][17];
    __shared__ float red[16][64];
    __shared__ float zrow[16];

    if (fl >= PROX + 1) {
        int d = t & 63, qd = t >> 6;
        float acc = 0.f;
        for (int c = qd * 256; c < qd * 256 + 256; ++c) acc += vb[(size_t)c * H + d];
        red[qd][d] = acc;
        __syncthreads();
        if (t < 64) {
            float tot = (red[0][t] + red[1][t] + red[2][t] + red[3][t]) * (1.0f / (float)S);
            for (int row = 0; row < 16; ++row) ob[(size_t)row * H + t] = tot;
        }
        return;
    }

    const int lo = max(fl - 1, 0);
    {
        const int row = t >> 4, lane = t & 15;
        const float* srow = scores + ((size_t)bh * S + (r0 + row)) * S;
        float m = -1e30f;
        for (int c = lo + lane; c < PROX; c += 16) m = fmaxf(m, srow[c]);
#pragma unroll
        for (int o = 8; o; o >>= 1) m = fmaxf(m, __shfl_xor_sync(0xffffffffu, m, o));
        float z = 0.f;
        for (int c = lo + lane; c < PROX; c += 16) {
            float e = expf(srow[c] - m);
            pt[c - lo][row] = e;
            z += e;
        }
#pragma unroll
        for (int o = 8; o; o >>= 1) z += __shfl_xor_sync(0xffffffffu, z, o);
        if (lane == 0) zrow[row] = z;
    }
    __syncthreads();

    float4 acc[16];
    if (t < 128) {
#pragma unroll
        for (int rr = 0; rr < 16; rr++) acc[rr] = make_float4(0.f, 0.f, 0.f, 0.f);
        const int dc = t & 15, g = t >> 4;
        for (int c = lo + g; c < PROX; c += 8) {
            float4 v4 = *(const float4*)(vb + (size_t)c * H + dc * 4);
            const float* pc = pt[c - lo];
#pragma unroll
            for (int rr = 0; rr < 16; rr++) {
                float p = pc[rr];
                acc[rr].x += p * v4.x; acc[rr].y += p * v4.y;
                acc[rr].z += p * v4.z; acc[rr].w += p * v4.w;
            }
        }
    }
    for (int gg = 0; gg < 8; gg++) {
        if (t < 128 && (t >> 4) == gg) {
            const int dc = t & 15;
#pragma unroll
            for (int rr = 0; rr < 16; rr++) {
                if (gg == 0) *(float4*)&red[rr][dc * 4] = acc[rr];
                else {
                    float4 cur = *(float4*)&red[rr][dc * 4];
                    cur.x += acc[rr].x; cur.y += acc[rr].y;
                    cur.z += acc[rr].z; cur.w += acc[rr].w;
                    *(float4*)&red[rr][dc * 4] = cur;
                }
            }
        }
        __syncthreads();
    }
    {
        int idx = t * 4;
        int row = idx >> 6, d = idx & 63;
        float invZ = 1.f / zrow[row];
        float4 o = make_float4(red[row][d] * invZ, red[row][d + 1] * invZ,
                               red[row][d + 2] * invZ, red[row][d + 3] * invZ);
        *(float4*)(ob + (size_t)row * H + d) = o;
    }
}

// ---------------------------------------------------------------------------
// Launch
// ---------------------------------------------------------------------------
extern "C" void kernel_launch(void* const* d_in, const int* in_sizes, int n_in,
                              void* d_out, int out_size)
{
    const float* hidden  = (const float*)d_in[0];
    const float* context = (const float*)d_in[1];
    const float* am      = (const float*)d_in[2];
    const float* gate    = (const float*)d_in[3];
    const float* vis     = (const float*)d_in[4];
    const float* Wq      = (const float*)d_in[5];
    const float* bq      = (const float*)d_in[6];
    const float* Wk      = (const float*)d_in[7];
    const float* bk      = (const float*)d_in[8];
    const float* Wv      = (const float*)d_in[9];
    const float* bv      = (const float*)d_in[10];
    const int*   feat    = (const int*)d_in[11];

    float* outp = (float*)d_out;
    float* scores;
    if ((size_t)out_size >= OUT_ELEMS + SCORES_ELEMS) {
        scores = outp + OUT_ELEMS;
    } else {
        void* p = nullptr;
        cudaGetSymbolAddress(&p, g_scores_fb);
        scores = (float*)p;
    }

    add_prep<<<(unsigned)(OUT_ELEMS / 4 / 256), 256>>>(hidden, context, vis, feat);
    {
        dim3 g((H * H / 4 + 255) / 256, 3);
        prep_w<<<g, 256>>>(Wq, Wk, Wv);
    }
    {
        dim3 grid(H / 128, M_TOT / 128, 3);
        qkv_mma<<<grid, 256>>>(bq, bk, bv);
    }
    {
        dim3 gb(PROX - 1, B * NH);
        band_scores<<<gb, 256>>>(gate, am, scores);
        dim3 gf(B * NH, 4);
        fullrow_scores<<<gf, 256>>>(gate, am, scores);
        dim3 gc(S / 64, (S - PROX) / 64, B * NH);
        block_scores<<<gc, 256>>>(gate, am, feat, scores);
    }
    {
        dim3 gt(PROX, B * NH);
        out_top<<<gt, 64>>>(scores, outp);
        dim3 gbm((S - PROX) / 16, B * NH);
        out_bottom<<<gbm, 256>>>(scores, feat, outp);
    }

    (void)in_sizes; (void)n_in;
}

// round 5
// speedup vs baseline: 1.5001x; 1.0557x over previous
#include <cuda_runtime.h>
#include <cuda_bf16.h>
#include <math.h>
#include <stdint.h>

// Problem constants
#define B  4
#define S  1024
#define H  768
#define NH 12
#define DH 64
#define PROX 512
#define NEGV (-100000.0f)
#define SCALE 0.125f

#define OUT_ELEMS    ((size_t)B * S * H)        // 3,145,728
#define SCORES_ELEMS ((size_t)B * NH * S * S)   // 50,331,648
#define M_TOT (B * S)                           // 4096

// ---------------------------------------------------------------------------
// Static device scratch
// ---------------------------------------------------------------------------
__device__ __nv_bfloat16 g_hs_hi [M_TOT * H];
__device__ __nv_bfloat16 g_hs_lo [M_TOT * H];
__device__ __nv_bfloat16 g_ctx_hi[M_TOT * H];
__device__ __nv_bfloat16 g_ctx_lo[M_TOT * H];
__device__ __nv_bfloat16 g_w_hi[3 * H * H];
__device__ __nv_bfloat16 g_w_lo[3 * H * H];
__device__ float g_q[M_TOT * H];
__device__ float g_k[M_TOT * H];
__device__ float g_v[M_TOT * H];
__device__ float g_scores_fb[B * NH * S * S];   // fallback only

// ---------------------------------------------------------------------------
// PTX helpers (sm_100 baseline: cp.async + ldmatrix + mma.sync)
// ---------------------------------------------------------------------------
__device__ __forceinline__ uint32_t smem_u32(const void* p) {
    uint32_t a;
    asm("{ .reg .u64 t; cvta.to.shared.u64 t, %1; cvt.u32.u64 %0, t; }" : "=r"(a) : "l"(p));
    return a;
}
#define CP_ASYNC16(saddr, gptr) \
    asm volatile("cp.async.cg.shared.global [%0], [%1], 16;" :: "r"(saddr), "l"(gptr))
#define CP_COMMIT  asm volatile("cp.async.commit_group;" ::: "memory")
#define CP_WAIT2   asm volatile("cp.async.wait_group 2;" ::: "memory")

__device__ __forceinline__ void ldsm_x4(uint32_t& r0, uint32_t& r1, uint32_t& r2,
                                        uint32_t& r3, uint32_t addr) {
    asm volatile("ldmatrix.sync.aligned.m8n8.x4.shared.b16 {%0,%1,%2,%3}, [%4];"
                 : "=r"(r0), "=r"(r1), "=r"(r2), "=r"(r3) : "r"(addr));
}
__device__ __forceinline__ void mma_bf16(float* d, uint32_t a0, uint32_t a1,
                                         uint32_t a2, uint32_t a3,
                                         uint32_t b0, uint32_t b1) {
    asm volatile(
        "mma.sync.aligned.m16n8k16.row.col.f32.bf16.bf16.f32 "
        "{%0,%1,%2,%3}, {%4,%5,%6,%7}, {%8,%9}, {%0,%1,%2,%3};"
        : "+f"(d[0]), "+f"(d[1]), "+f"(d[2]), "+f"(d[3])
        : "r"(a0), "r"(a1), "r"(a2), "r"(a3), "r"(b0), "r"(b1));
}

// ---------------------------------------------------------------------------
// Kernel 1: positional add + bf16 hi/lo split
// ---------------------------------------------------------------------------
struct bf4 { __nv_bfloat16 v[4]; };

__global__ void add_prep(const float* __restrict__ hidden,
                         const float* __restrict__ context,
                         const float* __restrict__ vis,
                         const int*   __restrict__ feat_len)
{
    size_t i4 = (size_t)blockIdx.x * blockDim.x + threadIdx.x;
    size_t base = i4 * 4;
    if (base >= OUT_ELEMS) return;
    int b = (int)(base / ((size_t)S * H));
    int s = (int)((base / H) % S);
    float4 h4 = ((const float4*)hidden)[i4];
    float4 c4 = ((const float4*)context)[i4];
    if (s < feat_len[b]) {
        float4 v4 = ((const float4*)vis)[i4];
        h4.x += v4.x; h4.y += v4.y; h4.z += v4.z; h4.w += v4.w;
        c4.x += v4.x; c4.y += v4.y; c4.z += v4.z; c4.w += v4.w;
    }
    float hv[4] = {h4.x, h4.y, h4.z, h4.w};
    float cv[4] = {c4.x, c4.y, c4.z, c4.w};
    bf4 hh, hl, ch, cl;
#pragma unroll
    for (int j = 0; j < 4; j++) {
        __nv_bfloat16 a = __float2bfloat16(hv[j]);
        hh.v[j] = a; hl.v[j] = __float2bfloat16(hv[j] - __bfloat162float(a));
        __nv_bfloat16 d = __float2bfloat16(cv[j]);
        ch.v[j] = d; cl.v[j] = __float2bfloat16(cv[j] - __bfloat162float(d));
    }
    ((bf4*)g_hs_hi)[i4]  = hh; ((bf4*)g_hs_lo)[i4]  = hl;
    ((bf4*)g_ctx_hi)[i4] = ch; ((bf4*)g_ctx_lo)[i4] = cl;
}

// ---------------------------------------------------------------------------
// Kernel 2: weight hi/lo split (z = 0,1,2 -> Wq,Wk,Wv)
// ---------------------------------------------------------------------------
__global__ void prep_w(const float* __restrict__ Wq, const float* __restrict__ Wk,
                       const float* __restrict__ Wv)
{
    const int z = blockIdx.y;
    const float* W = (z == 0) ? Wq : (z == 1) ? Wk : Wv;
    size_t i4 = (size_t)blockIdx.x * blockDim.x + threadIdx.x;
    if (i4 >= (size_t)H * H / 4) return;
    float4 w4 = ((const float4*)W)[i4];
    float wv[4] = {w4.x, w4.y, w4.z, w4.w};
    bf4 hi, lo;
#pragma unroll
    for (int j = 0; j < 4; j++) {
        __nv_bfloat16 a = __float2bfloat16(wv[j]);
        hi.v[j] = a; lo.v[j] = __float2bfloat16(wv[j] - __bfloat162float(a));
    }
    ((bf4*)(g_w_hi + (size_t)z * H * H))[i4] = hi;
    ((bf4*)(g_w_lo + (size_t)z * H * H))[i4] = lo;
}

// ---------------------------------------------------------------------------
// Kernel 3: QKV via mma.sync bf16 split GEMM, 4-stage cp.async pipeline.
// Y[m,n] = sum_k X[m,k] W[n,k] + bias, K' = 2304 (hi*hi + lo*hi + hi*lo)
// BM=128, BN=128, BK=32, 8 warps (4 along M x 2 along N), warp tile 32x64.
// grid = (768/128, 4096/128, 3), 256 threads, 80KB dynamic smem.
// ---------------------------------------------------------------------------
#define BKq 32
#define NROUNDS (3 * H / BKq)   // 72
#define SROW 80                 // smem row pitch (bytes): conflict-free ldmatrix
#define STILE (128 * SROW)      // 10240 bytes per tile buffer
#define NSTAGE 4
#define QKV_SMEM (2 * NSTAGE * STILE)   // 81920

__global__ void __launch_bounds__(256, 2)
qkv_mma(const float* __restrict__ bq, const float* __restrict__ bk,
        const float* __restrict__ bv)
{
    extern __shared__ char dsm[];

    const int z = blockIdx.z;
    const __nv_bfloat16* Ahi = (z == 0) ? g_hs_hi : g_ctx_hi;
    const __nv_bfloat16* Alo = (z == 0) ? g_hs_lo : g_ctx_lo;
    const __nv_bfloat16* Whi = g_w_hi + (size_t)z * H * H;
    const __nv_bfloat16* Wlo = g_w_lo + (size_t)z * H * H;
    const float* bias = (z == 0) ? bq : (z == 1) ? bk : bv;
    float* Y = (z == 0) ? g_q : (z == 1) ? g_k : g_v;

    const int m0 = blockIdx.y * 128;
    const int n0 = blockIdx.x * 128;
    const int tid = threadIdx.x;
    const int lane = tid & 31;
    const int wid = tid >> 5;
    const int warp_m = wid & 3;     // 0..3 -> 32-row slices
    const int warp_n = wid >> 2;    // 0..1 -> 64-col slices

    const uint32_t sA = smem_u32(dsm);                       // 4 stages A
    const uint32_t sB = sA + NSTAGE * STILE;                 // 4 stages B

    const int ldrow = tid >> 2;          // 0..63  (x2 iters -> 128 rows)
    const int ldch  = tid & 3;           // 16B chunk

    float acc[2][8][4];
#pragma unroll
    for (int i = 0; i < 2; i++)
#pragma unroll
        for (int j = 0; j < 8; j++)
#pragma unroll
            for (int q = 0; q < 4; q++) acc[i][j][q] = 0.f;

    // ---- stage loader (always followed by a commit by the caller) ----
    auto load_stage = [&](int r, int buf) {
        const int kp = r * BKq;
        const int phase = kp / H;
        const int k0 = kp % H;
        const __nv_bfloat16* As = (phase == 1) ? Alo : Ahi;
        const __nv_bfloat16* Bs = (phase == 2) ? Wlo : Whi;
        const uint32_t a_s = sA + buf * STILE;
        const uint32_t b_s = sB + buf * STILE;
#pragma unroll
        for (int i = 0; i < 2; i++) {
            int row = ldrow + i * 64;
            CP_ASYNC16(a_s + row * SROW + ldch * 16,
                       As + (size_t)(m0 + row) * H + k0 + ldch * 8);
        }
#pragma unroll
        for (int i = 0; i < 2; i++) {
            int row = ldrow + i * 64;
            CP_ASYNC16(b_s + row * SROW + ldch * 16,
                       Bs + (size_t)(n0 + row) * H + k0 + ldch * 8);
        }
    };

    // Prologue: stages 0..2 in flight
    load_stage(0, 0); CP_COMMIT;
    load_stage(1, 1); CP_COMMIT;
    load_stage(2, 2); CP_COMMIT;

    const uint32_t aBase = sA + (warp_m * 32 + (lane & 15)) * SROW + (lane >> 4) * 16;
    const uint32_t bBase = sB + (warp_n * 64 + ((lane >> 4) << 3) + (lane & 7)) * SROW
                         + ((lane >> 3) & 1) * 16;

    for (int r = 0; r < NROUNDS; r++) {
        const int buf = r & 3;
        CP_WAIT2;              // stage r complete (exactly 3 groups were pending)
        __syncthreads();       // all warps done computing stage r-1 & see stage r

        // issue stage r+3 into buffer (r+3)&3 == (r-1)&3 (safe: sync above)
        if (r + 3 < NROUNDS) load_stage(r + 3, (r + 3) & 3);
        CP_COMMIT;             // always commit to keep group accounting exact

#pragma unroll
        for (int kk = 0; kk < 2; kk++) {
            uint32_t a[2][4];
#pragma unroll
            for (int mt = 0; mt < 2; mt++)
                ldsm_x4(a[mt][0], a[mt][1], a[mt][2], a[mt][3],
                        aBase + buf * STILE + mt * 16 * SROW + kk * 32);
            uint32_t bfr[8][2];
#pragma unroll
            for (int nt2 = 0; nt2 < 4; nt2++) {
                uint32_t r0, r1, r2, r3;
                ldsm_x4(r0, r1, r2, r3,
                        bBase + buf * STILE + nt2 * 16 * SROW + kk * 32);
                bfr[nt2 * 2][0] = r0; bfr[nt2 * 2][1] = r1;
                bfr[nt2 * 2 + 1][0] = r2; bfr[nt2 * 2 + 1][1] = r3;
            }
#pragma unroll
            for (int mt = 0; mt < 2; mt++)
#pragma unroll
                for (int nt = 0; nt < 8; nt++)
                    mma_bf16(acc[mt][nt], a[mt][0], a[mt][1], a[mt][2], a[mt][3],
                             bfr[nt][0], bfr[nt][1]);
        }
    }

    // ---- epilogue: direct global stores + bias ----
#pragma unroll
    for (int mt = 0; mt < 2; mt++) {
        int mbase = m0 + warp_m * 32 + mt * 16 + (lane >> 2);
#pragma unroll
        for (int nt = 0; nt < 8; nt++) {
            int n = n0 + warp_n * 64 + nt * 8 + (lane & 3) * 2;
            float b0 = bias[n], b1 = bias[n + 1];
            float2 v0 = make_float2(acc[mt][nt][0] + b0, acc[mt][nt][1] + b1);
            float2 v1 = make_float2(acc[mt][nt][2] + b0, acc[mt][nt][3] + b1);
            *(float2*)(Y + (size_t)mbase * H + n) = v0;
            *(float2*)(Y + (size_t)(mbase + 8) * H + n) = v1;
        }
    }
}

// ---------------------------------------------------------------------------
// Kernel 4a: band rows (r in [0, PROX-1)) — NEG fill + 2 dots
// ---------------------------------------------------------------------------
__global__ void band_scores(const float* __restrict__ gate,
                            const float* __restrict__ am,
                            float* __restrict__ scores)
{
    const int r  = blockIdx.x;
    const int bh = blockIdx.y;
    const int b = bh / NH, h = bh % NH;
    float* srow = scores + ((size_t)bh * S + r) * S;
    const int t = threadIdx.x;

    float4 neg4 = make_float4(NEGV, NEGV, NEGV, NEGV);
    ((float4*)srow)[t] = neg4;
    __syncthreads();

    const int w = t >> 5, lane = t & 31;
    if (w < 2) {
        int c = r - w;
        if (c >= 0) {
            const float* qr = g_q + ((size_t)b * S + r) * H + h * DH;
            const float* kr = g_k + ((size_t)b * S + c) * H + h * DH;
            float p = qr[lane] * kr[lane] + qr[lane + 32] * kr[lane + 32];
#pragma unroll
            for (int o = 16; o; o >>= 1) p += __shfl_xor_sync(0xffffffffu, p, o);
            if (lane == 0)
                srow[c] = p * SCALE * gate[((size_t)b * S + r) * S + c] + am[(size_t)b * S + c];
        }
    }
}

// ---------------------------------------------------------------------------
// Kernel 4b: full row r = PROX-1.  grid = (B*NH, 4), 256 threads.
// ---------------------------------------------------------------------------
__global__ void fullrow_scores(const float* __restrict__ gate,
                               const float* __restrict__ am,
                               float* __restrict__ scores)
{
    const int bh = blockIdx.x;
    const int b = bh / NH, h = bh % NH;
    const int r = PROX - 1;
    __shared__ float qs[DH];
    const int t = threadIdx.x;
    if (t < DH) qs[t] = g_q[((size_t)b * S + r) * H + h * DH + t];
    __syncthreads();
    float* srow = scores + ((size_t)bh * S + r) * S;
    int c = blockIdx.y * 256 + t;
    const float4* k4 = (const float4*)(g_k + ((size_t)b * S + c) * H + h * DH);
    float acc = 0.f;
#pragma unroll
    for (int d4 = 0; d4 < 16; d4++) {
        float4 kv = k4[d4];
        acc += qs[d4 * 4 + 0] * kv.x + qs[d4 * 4 + 1] * kv.y
             + qs[d4 * 4 + 2] * kv.z + qs[d4 * 4 + 3] * kv.w;
    }
    srow[c] = acc * SCALE * gate[((size_t)b * S + r) * S + c] + am[(size_t)b * S + c];
}

// ---------------------------------------------------------------------------
// Kernel 4c: rows [PROX, S) — 64x64 tiles, compute [lo,PROX), NEG elsewhere
// ---------------------------------------------------------------------------
__global__ void __launch_bounds__(256)
block_scores(const float* __restrict__ gate,
             const float* __restrict__ am,
             const int*   __restrict__ feat_len,
             float* __restrict__ scores)
{
    const int bh = blockIdx.z;
    const int b = bh / NH, h = bh % NH;
    const int r0 = PROX + blockIdx.y * 64;
    const int c0 = blockIdx.x * 64;
    const int fl = feat_len[b];
    const int lo = max(fl - 1, 0);
    const int t = threadIdx.x;
    float* sbase = scores + ((size_t)bh * S + r0) * S;

    if (c0 >= PROX || c0 + 64 <= lo) {
        float4 neg4 = make_float4(NEGV, NEGV, NEGV, NEGV);
#pragma unroll
        for (int i = 0; i < 4; i++) {
            int idx = t + i * 256;
            int row = idx >> 4, col4 = idx & 15;
            *(float4*)(sbase + (size_t)row * S + c0 + col4 * 4) = neg4;
        }
        return;
    }

    __shared__ float Qs[64][65];
    __shared__ float Ks[64][65];
#pragma unroll
    for (int i = 0; i < 4; i++) {
        int idx = t + i * 256;
        int row = idx >> 4, f4 = idx & 15;
        float4 qv = *(const float4*)(g_q + ((size_t)(b * S + r0 + row)) * H + h * DH + f4 * 4);
        float4 kv = *(const float4*)(g_k + ((size_t)(b * S + c0 + row)) * H + h * DH + f4 * 4);
        Qs[row][f4 * 4 + 0] = qv.x; Qs[row][f4 * 4 + 1] = qv.y;
        Qs[row][f4 * 4 + 2] = qv.z; Qs[row][f4 * 4 + 3] = qv.w;
        Ks[row][f4 * 4 + 0] = kv.x; Ks[row][f4 * 4 + 1] = kv.y;
        Ks[row][f4 * 4 + 2] = kv.z; Ks[row][f4 * 4 + 3] = kv.w;
    }
    __syncthreads();

    const int tx = t & 15, ty = t >> 4;
    float acc[4][4];
#pragma unroll
    for (int i = 0; i < 4; i++)
#pragma unroll
        for (int j = 0; j < 4; j++) acc[i][j] = 0.f;

#pragma unroll 8
    for (int kk = 0; kk < 64; kk++) {
        float a[4], bb[4];
#pragma unroll
        for (int i = 0; i < 4; i++) a[i] = Qs[ty * 4 + i][kk];
#pragma unroll
        for (int j = 0; j < 4; j++) bb[j] = Ks[tx * 4 + j][kk];
#pragma unroll
        for (int i = 0; i < 4; i++)
#pragma unroll
            for (int j = 0; j < 4; j++) acc[i][j] += a[i] * bb[j];
    }

#pragma unroll
    for (int i = 0; i < 4; i++) {
        int rr = ty * 4 + i;
        int r = r0 + rr;
#pragma unroll
        for (int j = 0; j < 4; j++) {
            int c = c0 + tx * 4 + j;
            bool un = (c >= lo) && (c < PROX);
            float val = un
                ? acc[i][j] * SCALE * gate[((size_t)b * S + r) * S + c] + am[(size_t)b * S + c]
                : NEGV;
            sbase[(size_t)rr * S + c] = val;
        }
    }
}

// ---------------------------------------------------------------------------
// Kernel 5a: out rows [0, PROX)
// ---------------------------------------------------------------------------
__global__ void out_top(const float* __restrict__ scores, float* __restrict__ out)
{
    const int r  = blockIdx.x;
    const int bh = blockIdx.y;
    const int b = bh / NH, h = bh % NH;
    const int d = threadIdx.x;
    const float* srow = scores + ((size_t)bh * S + r) * S;
    const float* vb   = g_v + (size_t)b * S * H + h * DH;
    float* orow       = out + ((size_t)b * S + r) * H + h * DH;

    __shared__ float pr[S];
    __shared__ float red[2];

    if (r < PROX - 1) {
        float s1 = srow[r];
        float s0 = (r > 0) ? srow[r - 1] : -1e30f;
        float m = fmaxf(s0, s1);
        float e0 = expf(s0 - m), e1 = expf(s1 - m);
        float Z = e0 + e1;
        float val = e1 * vb[(size_t)r * H + d];
        if (r > 0) val += e0 * vb[(size_t)(r - 1) * H + d];
        orow[d] = val / Z;
    } else {
        float m = -1e30f;
        for (int c = d; c < S; c += 64) m = fmaxf(m, srow[c]);
#pragma unroll
        for (int o = 16; o; o >>= 1) m = fmaxf(m, __shfl_xor_sync(0xffffffffu, m, o));
        if ((d & 31) == 0) red[d >> 5] = m;
        __syncthreads();
        m = fmaxf(red[0], red[1]);
        __syncthreads();
        float z = 0.f;
        for (int c = d; c < S; c += 64) { float e = expf(srow[c] - m); pr[c] = e; z += e; }
#pragma unroll
        for (int o = 16; o; o >>= 1) z += __shfl_xor_sync(0xffffffffu, z, o);
        if ((d & 31) == 0) red[d >> 5] = z;
        __syncthreads();
        float Z = red[0] + red[1];
        float acc = 0.f;
        for (int c = 0; c < S; c++) acc += pr[c] * vb[(size_t)c * H + d];
        orow[d] = acc / Z;
    }
}

// ---------------------------------------------------------------------------
// Kernel 5b: out rows [PROX, S) — transposed probs, 16-row register reuse.
// grid = ((S-PROX)/16, B*NH), 256 threads.
// ---------------------------------------------------------------------------
__global__ void __launch_bounds__(256)
out_bottom(const float* __restrict__ scores, const int* __restrict__ feat_len,
           float* __restrict__ out)
{
    const int bh = blockIdx.y;
    const int b = bh / NH, h = bh % NH;
    const int r0 = PROX + blockIdx.x * 16;
    const int fl = feat_len[b];
    const int t = threadIdx.x;
    const float* vb = g_v + (size_t)b * S * H + h * DH;
    float* ob = out + ((size_t)b * S + r0) * H + h * DH;

    __shared__ float pt[512][17];
    __shared__ float red[16][64];
    __shared__ float zrow[16];

    if (fl >= PROX + 1) {
        int d = t & 63, qd = t >> 6;
        float acc = 0.f;
        for (int c = qd * 256; c < qd * 256 + 256; ++c) acc += vb[(size_t)c * H + d];
        red[qd][d] = acc;
        __syncthreads();
        if (t < 64) {
            float tot = (red[0][t] + red[1][t] + red[2][t] + red[3][t]) * (1.0f / (float)S);
            for (int row = 0; row < 16; ++row) ob[(size_t)row * H + t] = tot;
        }
        return;
    }

    const int lo = max(fl - 1, 0);
    {
        const int row = t >> 4, lane = t & 15;
        const float* srow = scores + ((size_t)bh * S + (r0 + row)) * S;
        float m = -1e30f;
        for (int c = lo + lane; c < PROX; c += 16) m = fmaxf(m, srow[c]);
#pragma unroll
        for (int o = 8; o; o >>= 1) m = fmaxf(m, __shfl_xor_sync(0xffffffffu, m, o));
        float z = 0.f;
        for (int c = lo + lane; c < PROX; c += 16) {
            float e = expf(srow[c] - m);
            pt[c - lo][row] = e;
            z += e;
        }
#pragma unroll
        for (int o = 8; o; o >>= 1) z += __shfl_xor_sync(0xffffffffu, z, o);
        if (lane == 0) zrow[row] = z;
    }
    __syncthreads();

    float4 acc[16];
    if (t < 128) {
#pragma unroll
        for (int rr = 0; rr < 16; rr++) acc[rr] = make_float4(0.f, 0.f, 0.f, 0.f);
        const int dc = t & 15, g = t >> 4;
        for (int c = lo + g; c < PROX; c += 8) {
            float4 v4 = *(const float4*)(vb + (size_t)c * H + dc * 4);
            const float* pc = pt[c - lo];
#pragma unroll
            for (int rr = 0; rr < 16; rr++) {
                float p = pc[rr];
                acc[rr].x += p * v4.x; acc[rr].y += p * v4.y;
                acc[rr].z += p * v4.z; acc[rr].w += p * v4.w;
            }
        }
    }
    for (int gg = 0; gg < 8; gg++) {
        if (t < 128 && (t >> 4) == gg) {
            const int dc = t & 15;
#pragma unroll
            for (int rr = 0; rr < 16; rr++) {
                if (gg == 0) *(float4*)&red[rr][dc * 4] = acc[rr];
                else {
                    float4 cur = *(float4*)&red[rr][dc * 4];
                    cur.x += acc[rr].x; cur.y += acc[rr].y;
                    cur.z += acc[rr].z; cur.w += acc[rr].w;
                    *(float4*)&red[rr][dc * 4] = cur;
                }
            }
        }
        __syncthreads();
    }
    {
        int idx = t * 4;
        int row = idx >> 6, d = idx & 63;
        float invZ = 1.f / zrow[row];
        float4 o = make_float4(red[row][d] * invZ, red[row][d + 1] * invZ,
                               red[row][d + 2] * invZ, red[row][d + 3] * invZ);
        *(float4*)(ob + (size_t)row * H + d) = o;
    }
}

// ---------------------------------------------------------------------------
// Launch
// ---------------------------------------------------------------------------
extern "C" void kernel_launch(void* const* d_in, const int* in_sizes, int n_in,
                              void* d_out, int out_size)
{
    const float* hidden  = (const float*)d_in[0];
    const float* context = (const float*)d_in[1];
    const float* am      = (const float*)d_in[2];
    const float* gate    = (const float*)d_in[3];
    const float* vis     = (const float*)d_in[4];
    const float* Wq      = (const float*)d_in[5];
    const float* bq      = (const float*)d_in[6];
    const float* Wk      = (const float*)d_in[7];
    const float* bk      = (const float*)d_in[8];
    const float* Wv      = (const float*)d_in[9];
    const float* bv      = (const float*)d_in[10];
    const int*   feat    = (const int*)d_in[11];

    float* outp = (float*)d_out;
    float* scores;
    if ((size_t)out_size >= OUT_ELEMS + SCORES_ELEMS) {
        scores = outp + OUT_ELEMS;
    } else {
        void* p = nullptr;
        cudaGetSymbolAddress(&p, g_scores_fb);
        scores = (float*)p;
    }

    cudaFuncSetAttribute(qkv_mma, cudaFuncAttributeMaxDynamicSharedMemorySize, QKV_SMEM);

    add_prep<<<(unsigned)(OUT_ELEMS / 4 / 256), 256>>>(hidden, context, vis, feat);
    {
        dim3 g((H * H / 4 + 255) / 256, 3);
        prep_w<<<g, 256>>>(Wq, Wk, Wv);
    }
    {
        dim3 grid(H / 128, M_TOT / 128, 3);
        qkv_mma<<<grid, 256, QKV_SMEM>>>(bq, bk, bv);
    }
    {
        dim3 gb(PROX - 1, B * NH);
        band_scores<<<gb, 256>>>(gate, am, scores);
        dim3 gf(B * NH, 4);
        fullrow_scores<<<gf, 256>>>(gate, am, scores);
        dim3 gc(S / 64, (S - PROX) / 64, B * NH);
        block_scores<<<gc, 256>>>(gate, am, feat, scores);
    }
    {
        dim3 gt(PROX, B * NH);
        out_top<<<gt, 64>>>(scores, outp);
        dim3 gbm((S - PROX) / 16, B * NH);
        out_bottom<<<gbm, 256>>>(scores, feat, outp);
    }

    (void)in_sizes; (void)n_in;
}

// round 8
// speedup vs baseline: 1.5948x; 1.0632x over previous
#include <cuda_runtime.h>
#include <cuda_bf16.h>
#include <cuda_fp16.h>
#include <math.h>
#include <stdint.h>

// Problem constants
#define B  4
#define S  1024
#define H  768
#define NH 12
#define DH 64
#define PROX 512
#define NEGV (-100000.0f)
#define SCALE 0.125f

#define OUT_ELEMS    ((size_t)B * S * H)        // 3,145,728
#define SCORES_ELEMS ((size_t)B * NH * S * S)   // 50,331,648
#define M_TOT (B * S)                           // 4096

// ---------------------------------------------------------------------------
// Static device scratch
// ---------------------------------------------------------------------------
__device__ __half        g_hs_h  [M_TOT * H];   // fp16 hidden+add  (Q input)
__device__ __half        g_ctx_h [M_TOT * H];   // fp16 context+add (K input)
__device__ __nv_bfloat16 g_ctx_hi[M_TOT * H];   // bf16 hi/lo ctx   (V input)
__device__ __nv_bfloat16 g_ctx_lo[M_TOT * H];
__device__ __half        g_wq_h[H * H];
__device__ __half        g_wk_h[H * H];
__device__ __nv_bfloat16 g_wv_hi[H * H];
__device__ __nv_bfloat16 g_wv_lo[H * H];
__device__ float g_q[M_TOT * H];
__device__ float g_k[M_TOT * H];
__device__ float g_v[M_TOT * H];
__device__ float g_scores_fb[B * NH * S * S];   // fallback only

// ---------------------------------------------------------------------------
// PTX helpers (sm_100 baseline: cp.async + ldmatrix + mma.sync)
// ---------------------------------------------------------------------------
__device__ __forceinline__ uint32_t smem_u32(const void* p) {
    uint32_t a;
    asm("{ .reg .u64 t; cvta.to.shared.u64 t, %1; cvt.u32.u64 %0, t; }" : "=r"(a) : "l"(p));
    return a;
}
#define CP_ASYNC16(saddr, gptr) \
    asm volatile("cp.async.cg.shared.global [%0], [%1], 16;" :: "r"(saddr), "l"(gptr))
#define CP_COMMIT  asm volatile("cp.async.commit_group;" ::: "memory")
#define CP_WAIT2   asm volatile("cp.async.wait_group 2;" ::: "memory")

__device__ __forceinline__ void ldsm_x4(uint32_t& r0, uint32_t& r1, uint32_t& r2,
                                        uint32_t& r3, uint32_t addr) {
    asm volatile("ldmatrix.sync.aligned.m8n8.x4.shared.b16 {%0,%1,%2,%3}, [%4];"
                 : "=r"(r0), "=r"(r1), "=r"(r2), "=r"(r3) : "r"(addr));
}
__device__ __forceinline__ void mma_bf16(float* d, uint32_t a0, uint32_t a1,
                                         uint32_t a2, uint32_t a3,
                                         uint32_t b0, uint32_t b1) {
    asm volatile(
        "mma.sync.aligned.m16n8k16.row.col.f32.bf16.bf16.f32 "
        "{%0,%1,%2,%3}, {%4,%5,%6,%7}, {%8,%9}, {%0,%1,%2,%3};"
        : "+f"(d[0]), "+f"(d[1]), "+f"(d[2]), "+f"(d[3])
        : "r"(a0), "r"(a1), "r"(a2), "r"(a3), "r"(b0), "r"(b1));
}
__device__ __forceinline__ void mma_f16(float* d, uint32_t a0, uint32_t a1,
                                        uint32_t a2, uint32_t a3,
                                        uint32_t b0, uint32_t b1) {
    asm volatile(
        "mma.sync.aligned.m16n8k16.row.col.f32.f16.f16.f32 "
        "{%0,%1,%2,%3}, {%4,%5,%6,%7}, {%8,%9}, {%0,%1,%2,%3};"
        : "+f"(d[0]), "+f"(d[1]), "+f"(d[2]), "+f"(d[3])
        : "r"(a0), "r"(a1), "r"(a2), "r"(a3), "r"(b0), "r"(b1));
}

// ---------------------------------------------------------------------------
// Kernel 1: positional add + per-path precision prep
// ---------------------------------------------------------------------------
struct h4v  { __half v[4]; };
struct bf4v { __nv_bfloat16 v[4]; };

__global__ void add_prep(const float* __restrict__ hidden,
                         const float* __restrict__ context,
                         const float* __restrict__ vis,
                         const int*   __restrict__ feat_len)
{
    size_t i4 = (size_t)blockIdx.x * blockDim.x + threadIdx.x;
    size_t base = i4 * 4;
    if (base >= OUT_ELEMS) return;
    int b = (int)(base / ((size_t)S * H));
    int s = (int)((base / H) % S);
    float4 h4 = ((const float4*)hidden)[i4];
    float4 c4 = ((const float4*)context)[i4];
    if (s < feat_len[b]) {
        float4 v4 = ((const float4*)vis)[i4];
        h4.x += v4.x; h4.y += v4.y; h4.z += v4.z; h4.w += v4.w;
        c4.x += v4.x; c4.y += v4.y; c4.z += v4.z; c4.w += v4.w;
    }
    float hv[4] = {h4.x, h4.y, h4.z, h4.w};
    float cv[4] = {c4.x, c4.y, c4.z, c4.w};
    h4v hh, chh; bf4v chi, clo;
#pragma unroll
    for (int j = 0; j < 4; j++) {
        hh.v[j]  = __float2half(hv[j]);
        chh.v[j] = __float2half(cv[j]);
        __nv_bfloat16 a = __float2bfloat16(cv[j]);
        chi.v[j] = a;
        clo.v[j] = __float2bfloat16(cv[j] - __bfloat162float(a));
    }
    ((h4v*)g_hs_h)[i4]   = hh;
    ((h4v*)g_ctx_h)[i4]  = chh;
    ((bf4v*)g_ctx_hi)[i4] = chi;
    ((bf4v*)g_ctx_lo)[i4] = clo;
}

// ---------------------------------------------------------------------------
// Kernel 2: weight prep.  z=0: Wq->fp16, z=1: Wk->fp16, z=2: Wv->bf16 hi/lo
// ---------------------------------------------------------------------------
__global__ void prep_w(const float* __restrict__ Wq, const float* __restrict__ Wk,
                       const float* __restrict__ Wv)
{
    const int z = blockIdx.y;
    size_t i4 = (size_t)blockIdx.x * blockDim.x + threadIdx.x;
    if (i4 >= (size_t)H * H / 4) return;
    if (z < 2) {
        const float* W = (z == 0) ? Wq : Wk;
        __half* D = (z == 0) ? g_wq_h : g_wk_h;
        float4 w4 = ((const float4*)W)[i4];
        h4v o;
        o.v[0] = __float2half(w4.x); o.v[1] = __float2half(w4.y);
        o.v[2] = __float2half(w4.z); o.v[3] = __float2half(w4.w);
        ((h4v*)D)[i4] = o;
    } else {
        float4 w4 = ((const float4*)Wv)[i4];
        float wv[4] = {w4.x, w4.y, w4.z, w4.w};
        bf4v hi, lo;
#pragma unroll
        for (int j = 0; j < 4; j++) {
            __nv_bfloat16 a = __float2bfloat16(wv[j]);
            hi.v[j] = a; lo.v[j] = __float2bfloat16(wv[j] - __bfloat162float(a));
        }
        ((bf4v*)g_wv_hi)[i4] = hi;
        ((bf4v*)g_wv_lo)[i4] = lo;
    }
}

// ---------------------------------------------------------------------------
// Kernel 3a/3b: QKV via mma.sync GEMM, 4-stage cp.async pipeline.
// qkv_mma_f16 : fp16 single-pass (K'=768, 24 rounds); z=0 -> Q, z=1 -> K
// qkv_mma_bf16: bf16 3-term     (K'=2304, 72 rounds); V
// BM=128, BN=128, BK=32, 8 warps (4 along M x 2 along N), warp tile 32x64.
// ---------------------------------------------------------------------------
#define BKq 32
#define SROW 80                 // smem row pitch (bytes): conflict-free ldmatrix
#define STILE (128 * SROW)      // 10240 bytes per tile buffer
#define NSTAGE 4
#define QKV_SMEM (2 * NSTAGE * STILE)   // 81920

__global__ void __launch_bounds__(256, 2)
qkv_mma_f16(const float* __restrict__ bq, const float* __restrict__ bk)
{
    extern __shared__ char dsm[];

    const uint16_t *Abase, *Wbase;
    const float* bias;
    float* Y;
    if (blockIdx.z == 0) {
        Abase = (const uint16_t*)g_hs_h;  Wbase = (const uint16_t*)g_wq_h;
        bias = bq; Y = g_q;
    } else {
        Abase = (const uint16_t*)g_ctx_h; Wbase = (const uint16_t*)g_wk_h;
        bias = bk; Y = g_k;
    }
    const int NR = H / BKq;     // 24

    const int m0 = blockIdx.y * 128;
    const int n0 = blockIdx.x * 128;
    const int tid = threadIdx.x;
    const int lane = tid & 31;
    const int wid = tid >> 5;
    const int warp_m = wid & 3;
    const int warp_n = wid >> 2;

    const uint32_t sA = smem_u32(dsm);
    const uint32_t sB = sA + NSTAGE * STILE;

    const int ldrow = tid >> 2;
    const int ldch  = tid & 3;

    float acc[2][8][4];
#pragma unroll
    for (int i = 0; i < 2; i++)
#pragma unroll
        for (int j = 0; j < 8; j++)
#pragma unroll
            for (int q = 0; q < 4; q++) acc[i][j][q] = 0.f;

    auto load_stage = [&](int r, int buf) {
        const int k0 = r * BKq;
        const uint32_t a_s = sA + buf * STILE;
        const uint32_t b_s = sB + buf * STILE;
#pragma unroll
        for (int i = 0; i < 2; i++) {
            int row = ldrow + i * 64;
            CP_ASYNC16(a_s + row * SROW + ldch * 16,
                       Abase + (size_t)(m0 + row) * H + k0 + ldch * 8);
        }
#pragma unroll
        for (int i = 0; i < 2; i++) {
            int row = ldrow + i * 64;
            CP_ASYNC16(b_s + row * SROW + ldch * 16,
                       Wbase + (size_t)(n0 + row) * H + k0 + ldch * 8);
        }
    };

    load_stage(0, 0); CP_COMMIT;
    load_stage(1, 1); CP_COMMIT;
    load_stage(2, 2); CP_COMMIT;

    const uint32_t aBase = sA + (warp_m * 32 + (lane & 15)) * SROW + (lane >> 4) * 16;
    const uint32_t bBase = sB + (warp_n * 64 + ((lane >> 4) << 3) + (lane & 7)) * SROW
                         + ((lane >> 3) & 1) * 16;

    for (int r = 0; r < NR; r++) {
        const int buf = r & 3;
        CP_WAIT2;
        __syncthreads();

        if (r + 3 < NR) load_stage(r + 3, (r + 3) & 3);
        CP_COMMIT;

#pragma unroll
        for (int kk = 0; kk < 2; kk++) {
            uint32_t a[2][4];
#pragma unroll
            for (int mt = 0; mt < 2; mt++)
                ldsm_x4(a[mt][0], a[mt][1], a[mt][2], a[mt][3],
                        aBase + buf * STILE + mt * 16 * SROW + kk * 32);
            uint32_t bfr[8][2];
#pragma unroll
            for (int nt2 = 0; nt2 < 4; nt2++) {
                uint32_t r0, r1, r2, r3;
                ldsm_x4(r0, r1, r2, r3,
                        bBase + buf * STILE + nt2 * 16 * SROW + kk * 32);
                bfr[nt2 * 2][0] = r0; bfr[nt2 * 2][1] = r1;
                bfr[nt2 * 2 + 1][0] = r2; bfr[nt2 * 2 + 1][1] = r3;
            }
#pragma unroll
            for (int mt = 0; mt < 2; mt++)
#pragma unroll
                for (int nt = 0; nt < 8; nt++)
                    mma_f16(acc[mt][nt], a[mt][0], a[mt][1], a[mt][2], a[mt][3],
                            bfr[nt][0], bfr[nt][1]);
        }
    }

#pragma unroll
    for (int mt = 0; mt < 2; mt++) {
        int mbase = m0 + warp_m * 32 + mt * 16 + (lane >> 2);
#pragma unroll
        for (int nt = 0; nt < 8; nt++) {
            int n = n0 + warp_n * 64 + nt * 8 + (lane & 3) * 2;
            float bb0 = bias[n], bb1 = bias[n + 1];
            float2 v0 = make_float2(acc[mt][nt][0] + bb0, acc[mt][nt][1] + bb1);
            float2 v1 = make_float2(acc[mt][nt][2] + bb0, acc[mt][nt][3] + bb1);
            *(float2*)(Y + (size_t)mbase * H + n) = v0;
            *(float2*)(Y + (size_t)(mbase + 8) * H + n) = v1;
        }
    }
}

__global__ void __launch_bounds__(256, 2)
qkv_mma_bf16(const float* __restrict__ bv)
{
    extern __shared__ char dsm[];

    const uint16_t* Ahi = (const uint16_t*)g_ctx_hi;
    const uint16_t* Alo = (const uint16_t*)g_ctx_lo;
    const uint16_t* Whi = (const uint16_t*)g_wv_hi;
    const uint16_t* Wlo = (const uint16_t*)g_wv_lo;
    const float* bias = bv;
    float* Y = g_v;
    const int NR = 3 * H / BKq;   // 72

    const int m0 = blockIdx.y * 128;
    const int n0 = blockIdx.x * 128;
    const int tid = threadIdx.x;
    const int lane = tid & 31;
    const int wid = tid >> 5;
    const int warp_m = wid & 3;
    const int warp_n = wid >> 2;

    const uint32_t sA = smem_u32(dsm);
    const uint32_t sB = sA + NSTAGE * STILE;

    const int ldrow = tid >> 2;
    const int ldch  = tid & 3;

    float acc[2][8][4];
#pragma unroll
    for (int i = 0; i < 2; i++)
#pragma unroll
        for (int j = 0; j < 8; j++)
#pragma unroll
            for (int q = 0; q < 4; q++) acc[i][j][q] = 0.f;

    auto load_stage = [&](int r, int buf) {
        const int kp = r * BKq;
        const int phase = kp / H;
        const int k0 = kp % H;
        const uint16_t* As = (phase == 1) ? Alo : Ahi;
        const uint16_t* Bs = (phase == 2) ? Wlo : Whi;
        const uint32_t a_s = sA + buf * STILE;
        const uint32_t b_s = sB + buf * STILE;
#pragma unroll
        for (int i = 0; i < 2; i++) {
            int row = ldrow + i * 64;
            CP_ASYNC16(a_s + row * SROW + ldch * 16,
                       As + (size_t)(m0 + row) * H + k0 + ldch * 8);
        }
#pragma unroll
        for (int i = 0; i < 2; i++) {
            int row = ldrow + i * 64;
            CP_ASYNC16(b_s + row * SROW + ldch * 16,
                       Bs + (size_t)(n0 + row) * H + k0 + ldch * 8);
        }
    };

    load_stage(0, 0); CP_COMMIT;
    load_stage(1, 1); CP_COMMIT;
    load_stage(2, 2); CP_COMMIT;

    const uint32_t aBase = sA + (warp_m * 32 + (lane & 15)) * SROW + (lane >> 4) * 16;
    const uint32_t bBase = sB + (warp_n * 64 + ((lane >> 4) << 3) + (lane & 7)) * SROW
                         + ((lane >> 3) & 1) * 16;

    for (int r = 0; r < NR; r++) {
        const int buf = r & 3;
        CP_WAIT2;
        __syncthreads();

        if (r + 3 < NR) load_stage(r + 3, (r + 3) & 3);
        CP_COMMIT;

#pragma unroll
        for (int kk = 0; kk < 2; kk++) {
            uint32_t a[2][4];
#pragma unroll
            for (int mt = 0; mt < 2; mt++)
                ldsm_x4(a[mt][0], a[mt][1], a[mt][2], a[mt][3],
                        aBase + buf * STILE + mt * 16 * SROW + kk * 32);
            uint32_t bfr[8][2];
#pragma unroll
            for (int nt2 = 0; nt2 < 4; nt2++) {
                uint32_t r0, r1, r2, r3;
                ldsm_x4(r0, r1, r2, r3,
                        bBase + buf * STILE + nt2 * 16 * SROW + kk * 32);
                bfr[nt2 * 2][0] = r0; bfr[nt2 * 2][1] = r1;
                bfr[nt2 * 2 + 1][0] = r2; bfr[nt2 * 2 + 1][1] = r3;
            }
#pragma unroll
            for (int mt = 0; mt < 2; mt++)
#pragma unroll
                for (int nt = 0; nt < 8; nt++)
                    mma_bf16(acc[mt][nt], a[mt][0], a[mt][1], a[mt][2], a[mt][3],
                             bfr[nt][0], bfr[nt][1]);
        }
    }

#pragma unroll
    for (int mt = 0; mt < 2; mt++) {
        int mbase = m0 + warp_m * 32 + mt * 16 + (lane >> 2);
#pragma unroll
        for (int nt = 0; nt < 8; nt++) {
            int n = n0 + warp_n * 64 + nt * 8 + (lane & 3) * 2;
            float bb0 = bias[n], bb1 = bias[n + 1];
            float2 v0 = make_float2(acc[mt][nt][0] + bb0, acc[mt][nt][1] + bb1);
            float2 v1 = make_float2(acc[mt][nt][2] + bb0, acc[mt][nt][3] + bb1);
            *(float2*)(Y + (size_t)mbase * H + n) = v0;
            *(float2*)(Y + (size_t)(mbase + 8) * H + n) = v1;
        }
    }
}

// ---------------------------------------------------------------------------
// Kernel 4a: band rows (r in [0, PROX-1)) — NEG fill + 2 dots
// ---------------------------------------------------------------------------
__global__ void band_scores(const float* __restrict__ gate,
                            const float* __restrict__ am,
                            float* __restrict__ scores)
{
    const int r  = blockIdx.x;
    const int bh = blockIdx.y;
    const int b = bh / NH, h = bh % NH;
    float* srow = scores + ((size_t)bh * S + r) * S;
    const int t = threadIdx.x;

    float4 neg4 = make_float4(NEGV, NEGV, NEGV, NEGV);
    ((float4*)srow)[t] = neg4;
    __syncthreads();

    const int w = t >> 5, lane = t & 31;
    if (w < 2) {
        int c = r - w;
        if (c >= 0) {
            const float* qr = g_q + ((size_t)b * S + r) * H + h * DH;
            const float* kr = g_k + ((size_t)b * S + c) * H + h * DH;
            float p = qr[lane] * kr[lane] + qr[lane + 32] * kr[lane + 32];
#pragma unroll
            for (int o = 16; o; o >>= 1) p += __shfl_xor_sync(0xffffffffu, p, o);
            if (lane == 0)
                srow[c] = p * SCALE * gate[((size_t)b * S + r) * S + c] + am[(size_t)b * S + c];
        }
    }
}

// ---------------------------------------------------------------------------
// Kernel 4b: full row r = PROX-1.  grid = (B*NH, 4), 256 threads.
// ---------------------------------------------------------------------------
__global__ void fullrow_scores(const float* __restrict__ gate,
                               const float* __restrict__ am,
                               float* __restrict__ scores)
{
    const int bh = blockIdx.x;
    const int b = bh / NH, h = bh % NH;
    const int r = PROX - 1;
    __shared__ float qs[DH];
    const int t = threadIdx.x;
    if (t < DH) qs[t] = g_q[((size_t)b * S + r) * H + h * DH + t];
    __syncthreads();
    float* srow = scores + ((size_t)bh * S + r) * S;
    int c = blockIdx.y * 256 + t;
    const float4* k4 = (const float4*)(g_k + ((size_t)b * S + c) * H + h * DH);
    float acc = 0.f;
#pragma unroll
    for (int d4 = 0; d4 < 16; d4++) {
        float4 kv = k4[d4];
        acc += qs[d4 * 4 + 0] * kv.x + qs[d4 * 4 + 1] * kv.y
             + qs[d4 * 4 + 2] * kv.z + qs[d4 * 4 + 3] * kv.w;
    }
    srow[c] = acc * SCALE * gate[((size_t)b * S + r) * S + c] + am[(size_t)b * S + c];
}

// ---------------------------------------------------------------------------
// Kernel 4c: rows [PROX, S) — 64x64 tiles, compute [lo,PROX), NEG elsewhere
// ---------------------------------------------------------------------------
__global__ void __launch_bounds__(256)
block_scores(const float* __restrict__ gate,
             const float* __restrict__ am,
             const int*   __restrict__ feat_len,
             float* __restrict__ scores)
{
    const int bh = blockIdx.z;
    const int b = bh / NH, h = bh % NH;
    const int r0 = PROX + blockIdx.y * 64;
    const int c0 = blockIdx.x * 64;
    const int fl = feat_len[b];
    const int lo = max(fl - 1, 0);
    const int t = threadIdx.x;
    float* sbase = scores + ((size_t)bh * S + r0) * S;

    if (c0 >= PROX || c0 + 64 <= lo) {
        float4 neg4 = make_float4(NEGV, NEGV, NEGV, NEGV);
#pragma unroll
        for (int i = 0; i < 4; i++) {
            int idx = t + i * 256;
            int row = idx >> 4, col4 = idx & 15;
            *(float4*)(sbase + (size_t)row * S + c0 + col4 * 4) = neg4;
        }
        return;
    }

    __shared__ float Qs[64][65];
    __shared__ float Ks[64][65];
#pragma unroll
    for (int i = 0; i < 4; i++) {
        int idx = t + i * 256;
        int row = idx >> 4, f4 = idx & 15;
        float4 qv = *(const float4*)(g_q + ((size_t)(b * S + r0 + row)) * H + h * DH + f4 * 4);
        float4 kv = *(const float4*)(g_k + ((size_t)(b * S + c0 + row)) * H + h * DH + f4 * 4);
        Qs[row][f4 * 4 + 0] = qv.x; Qs[row][f4 * 4 + 1] = qv.y;
        Qs[row][f4 * 4 + 2] = qv.z; Qs[row][f4 * 4 + 3] = qv.w;
        Ks[row][f4 * 4 + 0] = kv.x; Ks[row][f4 * 4 + 1] = kv.y;
        Ks[row][f4 * 4 + 2] = kv.z; Ks[row][f4 * 4 + 3] = kv.w;
    }
    __syncthreads();

    const int tx = t & 15, ty = t >> 4;
    float acc[4][4];
#pragma unroll
    for (int i = 0; i < 4; i++)
#pragma unroll
        for (int j = 0; j < 4; j++) acc[i][j] = 0.f;

#pragma unroll 8
    for (int kk = 0; kk < 64; kk++) {
        float a[4], bb[4];
#pragma unroll
        for (int i = 0; i < 4; i++) a[i] = Qs[ty * 4 + i][kk];
#pragma unroll
        for (int j = 0; j < 4; j++) bb[j] = Ks[tx * 4 + j][kk];
#pragma unroll
        for (int i = 0; i < 4; i++)
#pragma unroll
            for (int j = 0; j < 4; j++) acc[i][j] += a[i] * bb[j];
    }

#pragma unroll
    for (int i = 0; i < 4; i++) {
        int rr = ty * 4 + i;
        int r = r0 + rr;
#pragma unroll
        for (int j = 0; j < 4; j++) {
            int c = c0 + tx * 4 + j;
            bool un = (c >= lo) && (c < PROX);
            float val = un
                ? acc[i][j] * SCALE * gate[((size_t)b * S + r) * S + c] + am[(size_t)b * S + c]
                : NEGV;
            sbase[(size_t)rr * S + c] = val;
        }
    }
}

// ---------------------------------------------------------------------------
// Kernel 5a: out rows [0, PROX)
// ---------------------------------------------------------------------------
__global__ void out_top(const float* __restrict__ scores, float* __restrict__ out)
{
    const int r  = blockIdx.x;
    const int bh = blockIdx.y;
    const int b = bh / NH, h = bh % NH;
    const int d = threadIdx.x;
    const float* srow = scores + ((size_t)bh * S + r) * S;
    const float* vb   = g_v + (size_t)b * S * H + h * DH;
    float* orow       = out + ((size_t)b * S + r) * H + h * DH;

    __shared__ float pr[S];
    __shared__ float red[2];

    if (r < PROX - 1) {
        float s1 = srow[r];
        float s0 = (r > 0) ? srow[r - 1] : -1e30f;
        float m = fmaxf(s0, s1);
        float e0 = expf(s0 - m), e1 = expf(s1 - m);
        float Z = e0 + e1;
        float val = e1 * vb[(size_t)r * H + d];
        if (r > 0) val += e0 * vb[(size_t)(r - 1) * H + d];
        orow[d] = val / Z;
    } else {
        float m = -1e30f;
        for (int c = d; c < S; c += 64) m = fmaxf(m, srow[c]);
#pragma unroll
        for (int o = 16; o; o >>= 1) m = fmaxf(m, __shfl_xor_sync(0xffffffffu, m, o));
        if ((d & 31) == 0) red[d >> 5] = m;
        __syncthreads();
        m = fmaxf(red[0], red[1]);
        __syncthreads();
        float z = 0.f;
        for (int c = d; c < S; c += 64) { float e = expf(srow[c] - m); pr[c] = e; z += e; }
#pragma unroll
        for (int o = 16; o; o >>= 1) z += __shfl_xor_sync(0xffffffffu, z, o);
        if ((d & 31) == 0) red[d >> 5] = z;
        __syncthreads();
        float Z = red[0] + red[1];
        float acc = 0.f;
        for (int c = 0; c < S; c++) acc += pr[c] * vb[(size_t)c * H + d];
        orow[d] = acc / Z;
    }
}

// ---------------------------------------------------------------------------
// Kernel 5b: out rows [PROX, S) — transposed probs, 16-row register reuse.
// ---------------------------------------------------------------------------
__global__ void __launch_bounds__(256)
out_bottom(const float* __restrict__ scores, const int* __restrict__ feat_len,
           float* __restrict__ out)
{
    const int bh = blockIdx.y;
    const int b = bh / NH, h = bh % NH;
    const int r0 = PROX + blockIdx.x * 16;
    const int fl = feat_len[b];
    const int t = threadIdx.x;
    const float* vb = g_v + (size_t)b * S * H + h * DH;
    float* ob = out + ((size_t)b * S + r0) * H + h * DH;

    __shared__ float pt[512][17];
    __shared__ float red[16][64];
    __shared__ float zrow[16];

    if (fl >= PROX + 1) {
        int d = t & 63, qd = t >> 6;
        float acc = 0.f;
        for (int c = qd * 256; c < qd * 256 + 256; ++c) acc += vb[(size_t)c * H + d];
        red[qd][d] = acc;
        __syncthreads();
        if (t < 64) {
            float tot = (red[0][t] + red[1][t] + red[2][t] + red[3][t]) * (1.0f / (float)S);
            for (int row = 0; row < 16; ++row) ob[(size_t)row * H + t] = tot;
        }
        return;
    }

    const int lo = max(fl - 1, 0);
    {
        const int row = t >> 4, lane = t & 15;
        const float* srow = scores + ((size_t)bh * S + (r0 + row)) * S;
        float m = -1e30f;
        for (int c = lo + lane; c < PROX; c += 16) m = fmaxf(m, srow[c]);
#pragma unroll
        for (int o = 8; o; o >>= 1) m = fmaxf(m, __shfl_xor_sync(0xffffffffu, m, o));
        float z = 0.f;
        for (int c = lo + lane; c < PROX; c += 16) {
            float e = expf(srow[c] - m);
            pt[c - lo][row] = e;
            z += e;
        }
#pragma unroll
        for (int o = 8; o; o >>= 1) z += __shfl_xor_sync(0xffffffffu, z, o);
        if (lane == 0) zrow[row] = z;
    }
    __syncthreads();

    float4 acc[16];
    if (t < 128) {
#pragma unroll
        for (int rr = 0; rr < 16; rr++) acc[rr] = make_float4(0.f, 0.f, 0.f, 0.f);
        const int dc = t & 15, g = t >> 4;
        for (int c = lo + g; c < PROX; c += 8) {
            float4 v4 = *(const float4*)(vb + (size_t)c * H + dc * 4);
            const float* pc = pt[c - lo];
#pragma unroll
            for (int rr = 0; rr < 16; rr++) {
                float p = pc[rr];
                acc[rr].x += p * v4.x; acc[rr].y += p * v4.y;
                acc[rr].z += p * v4.z; acc[rr].w += p * v4.w;
            }
        }
    }
    for (int gg = 0; gg < 8; gg++) {
        if (t < 128 && (t >> 4) == gg) {
            const int dc = t & 15;
#pragma unroll
            for (int rr = 0; rr < 16; rr++) {
                if (gg == 0) *(float4*)&red[rr][dc * 4] = acc[rr];
                else {
                    float4 cur = *(float4*)&red[rr][dc * 4];
                    cur.x += acc[rr].x; cur.y += acc[rr].y;
                    cur.z += acc[rr].z; cur.w += acc[rr].w;
                    *(float4*)&red[rr][dc * 4] = cur;
                }
            }
        }
        __syncthreads();
    }
    {
        int idx = t * 4;
        int row = idx >> 6, d = idx & 63;
        float invZ = 1.f / zrow[row];
        float4 o = make_float4(red[row][d] * invZ, red[row][d + 1] * invZ,
                               red[row][d + 2] * invZ, red[row][d + 3] * invZ);
        *(float4*)(ob + (size_t)row * H + d) = o;
    }
}

// ---------------------------------------------------------------------------
// Launch
// ---------------------------------------------------------------------------
extern "C" void kernel_launch(void* const* d_in, const int* in_sizes, int n_in,
                              void* d_out, int out_size)
{
    const float* hidden  = (const float*)d_in[0];
    const float* context = (const float*)d_in[1];
    const float* am      = (const float*)d_in[2];
    const float* gate    = (const float*)d_in[3];
    const float* vis     = (const float*)d_in[4];
    const float* Wq      = (const float*)d_in[5];
    const float* bq      = (const float*)d_in[6];
    const float* Wk      = (const float*)d_in[7];
    const float* bk      = (const float*)d_in[8];
    const float* Wv      = (const float*)d_in[9];
    const float* bv      = (const float*)d_in[10];
    const int*   feat    = (const int*)d_in[11];

    float* outp = (float*)d_out;
    float* scores;
    if ((size_t)out_size >= OUT_ELEMS + SCORES_ELEMS) {
        scores = outp + OUT_ELEMS;
    } else {
        void* p = nullptr;
        cudaGetSymbolAddress(&p, g_scores_fb);
        scores = (float*)p;
    }

    cudaFuncSetAttribute(qkv_mma_f16,  cudaFuncAttributeMaxDynamicSharedMemorySize, QKV_SMEM);
    cudaFuncSetAttribute(qkv_mma_bf16, cudaFuncAttributeMaxDynamicSharedMemorySize, QKV_SMEM);

    add_prep<<<(unsigned)(OUT_ELEMS / 4 / 256), 256>>>(hidden, context, vis, feat);
    {
        dim3 g((H * H / 4 + 255) / 256, 3);
        prep_w<<<g, 256>>>(Wq, Wk, Wv);
    }
    {
        dim3 gridQK(H / 128, M_TOT / 128, 2);
        qkv_mma_f16<<<gridQK, 256, QKV_SMEM>>>(bq, bk);
        dim3 gridV(H / 128, M_TOT / 128, 1);
        qkv_mma_bf16<<<gridV, 256, QKV_SMEM>>>(bv);
    }
    {
        dim3 gb(PROX - 1, B * NH);
        band_scores<<<gb, 256>>>(gate, am, scores);
        dim3 gf(B * NH, 4);
        fullrow_scores<<<gf, 256>>>(gate, am, scores);
        dim3 gc(S / 64, (S - PROX) / 64, B * NH);
        block_scores<<<gc, 256>>>(gate, am, feat, scores);
    }
    {
        dim3 gt(PROX, B * NH);
        out_top<<<gt, 64>>>(scores, outp);
        dim3 gbm((S - PROX) / 16, B * NH);
        out_bottom<<<gbm, 256>>>(scores, feat, outp);
    }

    (void)in_sizes; (void)n_in;
}

// round 9
// speedup vs baseline: 1.6680x; 1.0459x over previous
#include <cuda_runtime.h>
#include <cuda_bf16.h>
#include <cuda_fp16.h>
#include <math.h>
#include <stdint.h>

// Problem constants
#define B  4
#define S  1024
#define H  768
#define NH 12
#define DH 64
#define PROX 512
#define NEGV (-100000.0f)
#define SCALE 0.125f

#define OUT_ELEMS    ((size_t)B * S * H)        // 3,145,728
#define SCORES_ELEMS ((size_t)B * NH * S * S)   // 50,331,648
#define M_TOT (B * S)                           // 4096

// ---------------------------------------------------------------------------
// Static device scratch
// ---------------------------------------------------------------------------
__device__ __half        g_hs_h  [M_TOT * H];   // fp16 hidden+add  (Q input)
__device__ __half        g_ctx_h [M_TOT * H];   // fp16 context+add (K input)
__device__ __nv_bfloat16 g_ctx_hi[M_TOT * H];   // bf16 hi/lo ctx   (V input)
__device__ __nv_bfloat16 g_ctx_lo[M_TOT * H];
__device__ __half        g_wq_h[H * H];
__device__ __half        g_wk_h[H * H];
__device__ __nv_bfloat16 g_wv_hi[H * H];
__device__ __nv_bfloat16 g_wv_lo[H * H];
__device__ float g_q[M_TOT * H];
__device__ float g_k[M_TOT * H];
__device__ float g_v[M_TOT * H];
__device__ __half g_qh[M_TOT * H];              // fp16 copies for score MMA
__device__ __half g_kh[M_TOT * H];
__device__ float g_scores_fb[B * NH * S * S];   // fallback only

// ---------------------------------------------------------------------------
// PTX helpers (sm_100 baseline: cp.async + ldmatrix + mma.sync)
// ---------------------------------------------------------------------------
__device__ __forceinline__ uint32_t smem_u32(const void* p) {
    uint32_t a;
    asm("{ .reg .u64 t; cvta.to.shared.u64 t, %1; cvt.u32.u64 %0, t; }" : "=r"(a) : "l"(p));
    return a;
}
#define CP_ASYNC16(saddr, gptr) \
    asm volatile("cp.async.cg.shared.global [%0], [%1], 16;" :: "r"(saddr), "l"(gptr))
#define CP_COMMIT  asm volatile("cp.async.commit_group;" ::: "memory")
#define CP_WAIT2   asm volatile("cp.async.wait_group 2;" ::: "memory")

__device__ __forceinline__ void ldsm_x4(uint32_t& r0, uint32_t& r1, uint32_t& r2,
                                        uint32_t& r3, uint32_t addr) {
    asm volatile("ldmatrix.sync.aligned.m8n8.x4.shared.b16 {%0,%1,%2,%3}, [%4];"
                 : "=r"(r0), "=r"(r1), "=r"(r2), "=r"(r3) : "r"(addr));
}
__device__ __forceinline__ void mma_bf16(float* d, uint32_t a0, uint32_t a1,
                                         uint32_t a2, uint32_t a3,
                                         uint32_t b0, uint32_t b1) {
    asm volatile(
        "mma.sync.aligned.m16n8k16.row.col.f32.bf16.bf16.f32 "
        "{%0,%1,%2,%3}, {%4,%5,%6,%7}, {%8,%9}, {%0,%1,%2,%3};"
        : "+f"(d[0]), "+f"(d[1]), "+f"(d[2]), "+f"(d[3])
        : "r"(a0), "r"(a1), "r"(a2), "r"(a3), "r"(b0), "r"(b1));
}
__device__ __forceinline__ void mma_f16(float* d, uint32_t a0, uint32_t a1,
                                        uint32_t a2, uint32_t a3,
                                        uint32_t b0, uint32_t b1) {
    asm volatile(
        "mma.sync.aligned.m16n8k16.row.col.f32.f16.f16.f32 "
        "{%0,%1,%2,%3}, {%4,%5,%6,%7}, {%8,%9}, {%0,%1,%2,%3};"
        : "+f"(d[0]), "+f"(d[1]), "+f"(d[2]), "+f"(d[3])
        : "r"(a0), "r"(a1), "r"(a2), "r"(a3), "r"(b0), "r"(b1));
}

// ---------------------------------------------------------------------------
// Kernel 1: positional add + per-path precision prep
// ---------------------------------------------------------------------------
struct h4v  { __half v[4]; };
struct bf4v { __nv_bfloat16 v[4]; };

__global__ void add_prep(const float* __restrict__ hidden,
                         const float* __restrict__ context,
                         const float* __restrict__ vis,
                         const int*   __restrict__ feat_len)
{
    size_t i4 = (size_t)blockIdx.x * blockDim.x + threadIdx.x;
    size_t base = i4 * 4;
    if (base >= OUT_ELEMS) return;
    int b = (int)(base / ((size_t)S * H));
    int s = (int)((base / H) % S);
    float4 h4 = ((const float4*)hidden)[i4];
    float4 c4 = ((const float4*)context)[i4];
    if (s < feat_len[b]) {
        float4 v4 = ((const float4*)vis)[i4];
        h4.x += v4.x; h4.y += v4.y; h4.z += v4.z; h4.w += v4.w;
        c4.x += v4.x; c4.y += v4.y; c4.z += v4.z; c4.w += v4.w;
    }
    float hv[4] = {h4.x, h4.y, h4.z, h4.w};
    float cv[4] = {c4.x, c4.y, c4.z, c4.w};
    h4v hh, chh; bf4v chi, clo;
#pragma unroll
    for (int j = 0; j < 4; j++) {
        hh.v[j]  = __float2half(hv[j]);
        chh.v[j] = __float2half(cv[j]);
        __nv_bfloat16 a = __float2bfloat16(cv[j]);
        chi.v[j] = a;
        clo.v[j] = __float2bfloat16(cv[j] - __bfloat162float(a));
    }
    ((h4v*)g_hs_h)[i4]   = hh;
    ((h4v*)g_ctx_h)[i4]  = chh;
    ((bf4v*)g_ctx_hi)[i4] = chi;
    ((bf4v*)g_ctx_lo)[i4] = clo;
}

// ---------------------------------------------------------------------------
// Kernel 2: weight prep.  z=0: Wq->fp16, z=1: Wk->fp16, z=2: Wv->bf16 hi/lo
// ---------------------------------------------------------------------------
__global__ void prep_w(const float* __restrict__ Wq, const float* __restrict__ Wk,
                       const float* __restrict__ Wv)
{
    const int z = blockIdx.y;
    size_t i4 = (size_t)blockIdx.x * blockDim.x + threadIdx.x;
    if (i4 >= (size_t)H * H / 4) return;
    if (z < 2) {
        const float* W = (z == 0) ? Wq : Wk;
        __half* D = (z == 0) ? g_wq_h : g_wk_h;
        float4 w4 = ((const float4*)W)[i4];
        h4v o;
        o.v[0] = __float2half(w4.x); o.v[1] = __float2half(w4.y);
        o.v[2] = __float2half(w4.z); o.v[3] = __float2half(w4.w);
        ((h4v*)D)[i4] = o;
    } else {
        float4 w4 = ((const float4*)Wv)[i4];
        float wv[4] = {w4.x, w4.y, w4.z, w4.w};
        bf4v hi, lo;
#pragma unroll
        for (int j = 0; j < 4; j++) {
            __nv_bfloat16 a = __float2bfloat16(wv[j]);
            hi.v[j] = a; lo.v[j] = __float2bfloat16(wv[j] - __bfloat162float(a));
        }
        ((bf4v*)g_wv_hi)[i4] = hi;
        ((bf4v*)g_wv_lo)[i4] = lo;
    }
}

// ---------------------------------------------------------------------------
// Kernel 3a/3b: QKV via mma.sync GEMM, 4-stage cp.async pipeline.
// qkv_mma_f16 : fp16 single-pass (K'=768, 24 rounds); z=0 -> Q, z=1 -> K
//               epilogue ALSO stores fp16 copies g_qh / g_kh
// qkv_mma_bf16: bf16 3-term     (K'=2304, 72 rounds); V
// ---------------------------------------------------------------------------
#define BKq 32
#define SROW 80                 // smem row pitch (bytes): conflict-free ldmatrix
#define STILE (128 * SROW)      // 10240 bytes per tile buffer
#define NSTAGE 4
#define QKV_SMEM (2 * NSTAGE * STILE)   // 81920

__global__ void __launch_bounds__(256, 2)
qkv_mma_f16(const float* __restrict__ bq, const float* __restrict__ bk)
{
    extern __shared__ char dsm[];

    const uint16_t *Abase, *Wbase;
    const float* bias;
    float* Y;
    __half* Yh;
    if (blockIdx.z == 0) {
        Abase = (const uint16_t*)g_hs_h;  Wbase = (const uint16_t*)g_wq_h;
        bias = bq; Y = g_q; Yh = g_qh;
    } else {
        Abase = (const uint16_t*)g_ctx_h; Wbase = (const uint16_t*)g_wk_h;
        bias = bk; Y = g_k; Yh = g_kh;
    }
    const int NR = H / BKq;     // 24

    const int m0 = blockIdx.y * 128;
    const int n0 = blockIdx.x * 128;
    const int tid = threadIdx.x;
    const int lane = tid & 31;
    const int wid = tid >> 5;
    const int warp_m = wid & 3;
    const int warp_n = wid >> 2;

    const uint32_t sA = smem_u32(dsm);
    const uint32_t sB = sA + NSTAGE * STILE;

    const int ldrow = tid >> 2;
    const int ldch  = tid & 3;

    float acc[2][8][4];
#pragma unroll
    for (int i = 0; i < 2; i++)
#pragma unroll
        for (int j = 0; j < 8; j++)
#pragma unroll
            for (int q = 0; q < 4; q++) acc[i][j][q] = 0.f;

    auto load_stage = [&](int r, int buf) {
        const int k0 = r * BKq;
        const uint32_t a_s = sA + buf * STILE;
        const uint32_t b_s = sB + buf * STILE;
#pragma unroll
        for (int i = 0; i < 2; i++) {
            int row = ldrow + i * 64;
            CP_ASYNC16(a_s + row * SROW + ldch * 16,
                       Abase + (size_t)(m0 + row) * H + k0 + ldch * 8);
        }
#pragma unroll
        for (int i = 0; i < 2; i++) {
            int row = ldrow + i * 64;
            CP_ASYNC16(b_s + row * SROW + ldch * 16,
                       Wbase + (size_t)(n0 + row) * H + k0 + ldch * 8);
        }
    };

    load_stage(0, 0); CP_COMMIT;
    load_stage(1, 1); CP_COMMIT;
    load_stage(2, 2); CP_COMMIT;

    const uint32_t aBase = sA + (warp_m * 32 + (lane & 15)) * SROW + (lane >> 4) * 16;
    const uint32_t bBase = sB + (warp_n * 64 + ((lane >> 4) << 3) + (lane & 7)) * SROW
                         + ((lane >> 3) & 1) * 16;

    for (int r = 0; r < NR; r++) {
        const int buf = r & 3;
        CP_WAIT2;
        __syncthreads();

        if (r + 3 < NR) load_stage(r + 3, (r + 3) & 3);
        CP_COMMIT;

#pragma unroll
        for (int kk = 0; kk < 2; kk++) {
            uint32_t a[2][4];
#pragma unroll
            for (int mt = 0; mt < 2; mt++)
                ldsm_x4(a[mt][0], a[mt][1], a[mt][2], a[mt][3],
                        aBase + buf * STILE + mt * 16 * SROW + kk * 32);
            uint32_t bfr[8][2];
#pragma unroll
            for (int nt2 = 0; nt2 < 4; nt2++) {
                uint32_t r0, r1, r2, r3;
                ldsm_x4(r0, r1, r2, r3,
                        bBase + buf * STILE + nt2 * 16 * SROW + kk * 32);
                bfr[nt2 * 2][0] = r0; bfr[nt2 * 2][1] = r1;
                bfr[nt2 * 2 + 1][0] = r2; bfr[nt2 * 2 + 1][1] = r3;
            }
#pragma unroll
            for (int mt = 0; mt < 2; mt++)
#pragma unroll
                for (int nt = 0; nt < 8; nt++)
                    mma_f16(acc[mt][nt], a[mt][0], a[mt][1], a[mt][2], a[mt][3],
                            bfr[nt][0], bfr[nt][1]);
        }
    }

#pragma unroll
    for (int mt = 0; mt < 2; mt++) {
        int mbase = m0 + warp_m * 32 + mt * 16 + (lane >> 2);
#pragma unroll
        for (int nt = 0; nt < 8; nt++) {
            int n = n0 + warp_n * 64 + nt * 8 + (lane & 3) * 2;
            float bb0 = bias[n], bb1 = bias[n + 1];
            float2 v0 = make_float2(acc[mt][nt][0] + bb0, acc[mt][nt][1] + bb1);
            float2 v1 = make_float2(acc[mt][nt][2] + bb0, acc[mt][nt][3] + bb1);
            *(float2*)(Y + (size_t)mbase * H + n) = v0;
            *(float2*)(Y + (size_t)(mbase + 8) * H + n) = v1;
            *(__half2*)(Yh + (size_t)mbase * H + n) = __floats2half2_rn(v0.x, v0.y);
            *(__half2*)(Yh + (size_t)(mbase + 8) * H + n) = __floats2half2_rn(v1.x, v1.y);
        }
    }
}

__global__ void __launch_bounds__(256, 2)
qkv_mma_bf16(const float* __restrict__ bv)
{
    extern __shared__ char dsm[];

    const uint16_t* Ahi = (const uint16_t*)g_ctx_hi;
    const uint16_t* Alo = (const uint16_t*)g_ctx_lo;
    const uint16_t* Whi = (const uint16_t*)g_wv_hi;
    const uint16_t* Wlo = (const uint16_t*)g_wv_lo;
    const float* bias = bv;
    float* Y = g_v;
    const int NR = 3 * H / BKq;   // 72

    const int m0 = blockIdx.y * 128;
    const int n0 = blockIdx.x * 128;
    const int tid = threadIdx.x;
    const int lane = tid & 31;
    const int wid = tid >> 5;
    const int warp_m = wid & 3;
    const int warp_n = wid >> 2;

    const uint32_t sA = smem_u32(dsm);
    const uint32_t sB = sA + NSTAGE * STILE;

    const int ldrow = tid >> 2;
    const int ldch  = tid & 3;

    float acc[2][8][4];
#pragma unroll
    for (int i = 0; i < 2; i++)
#pragma unroll
        for (int j = 0; j < 8; j++)
#pragma unroll
            for (int q = 0; q < 4; q++) acc[i][j][q] = 0.f;

    auto load_stage = [&](int r, int buf) {
        const int kp = r * BKq;
        const int phase = kp / H;
        const int k0 = kp % H;
        const uint16_t* As = (phase == 1) ? Alo : Ahi;
        const uint16_t* Bs = (phase == 2) ? Wlo : Whi;
        const uint32_t a_s = sA + buf * STILE;
        const uint32_t b_s = sB + buf * STILE;
#pragma unroll
        for (int i = 0; i < 2; i++) {
            int row = ldrow + i * 64;
            CP_ASYNC16(a_s + row * SROW + ldch * 16,
                       As + (size_t)(m0 + row) * H + k0 + ldch * 8);
        }
#pragma unroll
        for (int i = 0; i < 2; i++) {
            int row = ldrow + i * 64;
            CP_ASYNC16(b_s + row * SROW + ldch * 16,
                       Bs + (size_t)(n0 + row) * H + k0 + ldch * 8);
        }
    };

    load_stage(0, 0); CP_COMMIT;
    load_stage(1, 1); CP_COMMIT;
    load_stage(2, 2); CP_COMMIT;

    const uint32_t aBase = sA + (warp_m * 32 + (lane & 15)) * SROW + (lane >> 4) * 16;
    const uint32_t bBase = sB + (warp_n * 64 + ((lane >> 4) << 3) + (lane & 7)) * SROW
                         + ((lane >> 3) & 1) * 16;

    for (int r = 0; r < NR; r++) {
        const int buf = r & 3;
        CP_WAIT2;
        __syncthreads();

        if (r + 3 < NR) load_stage(r + 3, (r + 3) & 3);
        CP_COMMIT;

#pragma unroll
        for (int kk = 0; kk < 2; kk++) {
            uint32_t a[2][4];
#pragma unroll
            for (int mt = 0; mt < 2; mt++)
                ldsm_x4(a[mt][0], a[mt][1], a[mt][2], a[mt][3],
                        aBase + buf * STILE + mt * 16 * SROW + kk * 32);
            uint32_t bfr[8][2];
#pragma unroll
            for (int nt2 = 0; nt2 < 4; nt2++) {
                uint32_t r0, r1, r2, r3;
                ldsm_x4(r0, r1, r2, r3,
                        bBase + buf * STILE + nt2 * 16 * SROW + kk * 32);
                bfr[nt2 * 2][0] = r0; bfr[nt2 * 2][1] = r1;
                bfr[nt2 * 2 + 1][0] = r2; bfr[nt2 * 2 + 1][1] = r3;
            }
#pragma unroll
            for (int mt = 0; mt < 2; mt++)
#pragma unroll
                for (int nt = 0; nt < 8; nt++)
                    mma_bf16(acc[mt][nt], a[mt][0], a[mt][1], a[mt][2], a[mt][3],
                             bfr[nt][0], bfr[nt][1]);
        }
    }

#pragma unroll
    for (int mt = 0; mt < 2; mt++) {
        int mbase = m0 + warp_m * 32 + mt * 16 + (lane >> 2);
#pragma unroll
        for (int nt = 0; nt < 8; nt++) {
            int n = n0 + warp_n * 64 + nt * 8 + (lane & 3) * 2;
            float bb0 = bias[n], bb1 = bias[n + 1];
            float2 v0 = make_float2(acc[mt][nt][0] + bb0, acc[mt][nt][1] + bb1);
            float2 v1 = make_float2(acc[mt][nt][2] + bb0, acc[mt][nt][3] + bb1);
            *(float2*)(Y + (size_t)mbase * H + n) = v0;
            *(float2*)(Y + (size_t)(mbase + 8) * H + n) = v1;
        }
    }
}

// ---------------------------------------------------------------------------
// Kernel 4a: band rows (r in [0, PROX-1)) — NEG fill + 2 dots
// ---------------------------------------------------------------------------
__global__ void band_scores(const float* __restrict__ gate,
                            const float* __restrict__ am,
                            float* __restrict__ scores)
{
    const int r  = blockIdx.x;
    const int bh = blockIdx.y;
    const int b = bh / NH, h = bh % NH;
    float* srow = scores + ((size_t)bh * S + r) * S;
    const int t = threadIdx.x;

    float4 neg4 = make_float4(NEGV, NEGV, NEGV, NEGV);
    ((float4*)srow)[t] = neg4;
    __syncthreads();

    const int w = t >> 5, lane = t & 31;
    if (w < 2) {
        int c = r - w;
        if (c >= 0) {
            const float* qr = g_q + ((size_t)b * S + r) * H + h * DH;
            const float* kr = g_k + ((size_t)b * S + c) * H + h * DH;
            float p = qr[lane] * kr[lane] + qr[lane + 32] * kr[lane + 32];
#pragma unroll
            for (int o = 16; o; o >>= 1) p += __shfl_xor_sync(0xffffffffu, p, o);
            if (lane == 0)
                srow[c] = p * SCALE * gate[((size_t)b * S + r) * S + c] + am[(size_t)b * S + c];
        }
    }
}

// ---------------------------------------------------------------------------
// Kernel 4b: full row r = PROX-1.  grid = (B*NH, 4), 256 threads.
// ---------------------------------------------------------------------------
__global__ void fullrow_scores(const float* __restrict__ gate,
                               const float* __restrict__ am,
                               float* __restrict__ scores)
{
    const int bh = blockIdx.x;
    const int b = bh / NH, h = bh % NH;
    const int r = PROX - 1;
    __shared__ float qs[DH];
    const int t = threadIdx.x;
    if (t < DH) qs[t] = g_q[((size_t)b * S + r) * H + h * DH + t];
    __syncthreads();
    float* srow = scores + ((size_t)bh * S + r) * S;
    int c = blockIdx.y * 256 + t;
    const float4* k4 = (const float4*)(g_k + ((size_t)b * S + c) * H + h * DH);
    float acc = 0.f;
#pragma unroll
    for (int d4 = 0; d4 < 16; d4++) {
        float4 kv = k4[d4];
        acc += qs[d4 * 4 + 0] * kv.x + qs[d4 * 4 + 1] * kv.y
             + qs[d4 * 4 + 2] * kv.z + qs[d4 * 4 + 3] * kv.w;
    }
    srow[c] = acc * SCALE * gate[((size_t)b * S + r) * S + c] + am[(size_t)b * S + c];
}

// ---------------------------------------------------------------------------
// Kernel 4c: rows [PROX, S) — 64x64 tiles via fp16 mma.sync.
// Compute cols [lo, PROX), NEG elsewhere.  grid = (16, 8, 48), 256 threads.
// ---------------------------------------------------------------------------
#define BSROW 144   // fp16 tile pitch in bytes (72 halves): conflict-free ldmatrix

__global__ void __launch_bounds__(256)
block_scores(const float* __restrict__ gate,
             const float* __restrict__ am,
             const int*   __restrict__ feat_len,
             float* __restrict__ scores)
{
    const int bh = blockIdx.z;
    const int b = bh / NH, h = bh % NH;
    const int r0 = PROX + blockIdx.y * 64;
    const int c0 = blockIdx.x * 64;
    const int fl = feat_len[b];
    const int lo = max(fl - 1, 0);
    const int t = threadIdx.x;
    float* sbase = scores + ((size_t)bh * S + r0) * S;

    if (c0 >= PROX || c0 + 64 <= lo) {
        float4 neg4 = make_float4(NEGV, NEGV, NEGV, NEGV);
#pragma unroll
        for (int i = 0; i < 4; i++) {
            int idx = t + i * 256;
            int row = idx >> 4, col4 = idx & 15;
            *(float4*)(sbase + (size_t)row * S + c0 + col4 * 4) = neg4;
        }
        return;
    }

    __shared__ __align__(16) char Qs[64 * BSROW];
    __shared__ __align__(16) char Ks[64 * BSROW];
    __shared__ float Ds[64][68];

    const uint32_t sQ = smem_u32(Qs);
    const uint32_t sK = smem_u32(Ks);

    // load tiles: 64 rows x 128B each = 512 x 16B chunks per tile; 2 chunks/thread
    {
        const __half* qsrc = g_qh + ((size_t)b * S + r0) * H + h * DH;
        const __half* ksrc = g_kh + ((size_t)b * S + c0) * H + h * DH;
#pragma unroll
        for (int i = 0; i < 2; i++) {
            int id = t + i * 256;
            int row = id >> 3, ch = id & 7;
            *(uint4*)(Qs + row * BSROW + ch * 16) =
                *(const uint4*)(qsrc + (size_t)row * H + ch * 8);
            *(uint4*)(Ks + row * BSROW + ch * 16) =
                *(const uint4*)(ksrc + (size_t)row * H + ch * 8);
        }
    }
    __syncthreads();

    const int lane = t & 31;
    const int wid = t >> 5;
    const int warp_m = wid & 3;    // 16-row slice
    const int warp_n = wid >> 2;   // 32-col slice

    float acc[4][4];
#pragma unroll
    for (int i = 0; i < 4; i++)
#pragma unroll
        for (int j = 0; j < 4; j++) acc[i][j] = 0.f;

    const uint32_t aBase = sQ + (warp_m * 16 + (lane & 15)) * BSROW + (lane >> 4) * 16;
    const uint32_t bBase = sK + (warp_n * 32 + ((lane >> 4) << 3) + (lane & 7)) * BSROW
                         + ((lane >> 3) & 1) * 16;

#pragma unroll
    for (int kk = 0; kk < 4; kk++) {         // 4 k-steps of 16
        uint32_t a0, a1, a2, a3;
        ldsm_x4(a0, a1, a2, a3, aBase + kk * 32);
        uint32_t bfr[4][2];
#pragma unroll
        for (int nt2 = 0; nt2 < 2; nt2++) {
            uint32_t r0r, r1r, r2r, r3r;
            ldsm_x4(r0r, r1r, r2r, r3r, bBase + nt2 * 16 * BSROW + kk * 32);
            bfr[nt2 * 2][0] = r0r; bfr[nt2 * 2][1] = r1r;
            bfr[nt2 * 2 + 1][0] = r2r; bfr[nt2 * 2 + 1][1] = r3r;
        }
#pragma unroll
        for (int nt = 0; nt < 4; nt++)
            mma_f16(acc[nt], a0, a1, a2, a3, bfr[nt][0], bfr[nt][1]);
    }

    // store fragments into Ds
#pragma unroll
    for (int nt = 0; nt < 4; nt++) {
        int row = warp_m * 16 + (lane >> 2);
        int col = warp_n * 32 + nt * 8 + (lane & 3) * 2;
        Ds[row][col]     = acc[nt][0];
        Ds[row][col + 1] = acc[nt][1];
        Ds[row + 8][col]     = acc[nt][2];
        Ds[row + 8][col + 1] = acc[nt][3];
    }
    __syncthreads();

    // epilogue: gate/am/NEG + coalesced stores (same pattern as before)
    const int tx = t & 15, ty = t >> 4;
#pragma unroll
    for (int i = 0; i < 4; i++) {
        int rr = ty * 4 + i;
        int r = r0 + rr;
        float4 o;
        float* op = &o.x;
#pragma unroll
        for (int j = 0; j < 4; j++) {
            int c = c0 + tx * 4 + j;
            bool un = (c >= lo) && (c < PROX);
            op[j] = un
                ? Ds[rr][tx * 4 + j] * SCALE * gate[((size_t)b * S + r) * S + c]
                  + am[(size_t)b * S + c]
                : NEGV;
        }
        *(float4*)(sbase + (size_t)rr * S + c0 + tx * 4) = o;
    }
}

// ---------------------------------------------------------------------------
// Kernel 5a: out rows [0, PROX)
// ---------------------------------------------------------------------------
__global__ void out_top(const float* __restrict__ scores, float* __restrict__ out)
{
    const int r  = blockIdx.x;
    const int bh = blockIdx.y;
    const int b = bh / NH, h = bh % NH;
    const int d = threadIdx.x;
    const float* srow = scores + ((size_t)bh * S + r) * S;
    const float* vb   = g_v + (size_t)b * S * H + h * DH;
    float* orow       = out + ((size_t)b * S + r) * H + h * DH;

    __shared__ float pr[S];
    __shared__ float red[2];

    if (r < PROX - 1) {
        float s1 = srow[r];
        float s0 = (r > 0) ? srow[r - 1] : -1e30f;
        float m = fmaxf(s0, s1);
        float e0 = expf(s0 - m), e1 = expf(s1 - m);
        float Z = e0 + e1;
        float val = e1 * vb[(size_t)r * H + d];
        if (r > 0) val += e0 * vb[(size_t)(r - 1) * H + d];
        orow[d] = val / Z;
    } else {
        float m = -1e30f;
        for (int c = d; c < S; c += 64) m = fmaxf(m, srow[c]);
#pragma unroll
        for (int o = 16; o; o >>= 1) m = fmaxf(m, __shfl_xor_sync(0xffffffffu, m, o));
        if ((d & 31) == 0) red[d >> 5] = m;
        __syncthreads();
        m = fmaxf(red[0], red[1]);
        __syncthreads();
        float z = 0.f;
        for (int c = d; c < S; c += 64) { float e = expf(srow[c] - m); pr[c] = e; z += e; }
#pragma unroll
        for (int o = 16; o; o >>= 1) z += __shfl_xor_sync(0xffffffffu, z, o);
        if ((d & 31) == 0) red[d >> 5] = z;
        __syncthreads();
        float Z = red[0] + red[1];
        float acc = 0.f;
        for (int c = 0; c < S; c++) acc += pr[c] * vb[(size_t)c * H + d];
        orow[d] = acc / Z;
    }
}

// ---------------------------------------------------------------------------
// Kernel 5b: out rows [PROX, S) — transposed probs, 16-row register reuse.
// ---------------------------------------------------------------------------
__global__ void __launch_bounds__(256)
out_bottom(const float* __restrict__ scores, const int* __restrict__ feat_len,
           float* __restrict__ out)
{
    const int bh = blockIdx.y;
    const int b = bh / NH, h = bh % NH;
    const int r0 = PROX + blockIdx.x * 16;
    const int fl = feat_len[b];
    const int t = threadIdx.x;
    const float* vb = g_v + (size_t)b * S * H + h * DH;
    float* ob = out + ((size_t)b * S + r0) * H + h * DH;

    __shared__ float pt[512][17];
    __shared__ float red[16][64];
    __shared__ float zrow[16];

    if (fl >= PROX + 1) {
        int d = t & 63, qd = t >> 6;
        float acc = 0.f;
        for (int c = qd * 256; c < qd * 256 + 256; ++c) acc += vb[(size_t)c * H + d];
        red[qd][d] = acc;
        __syncthreads();
        if (t < 64) {
            float tot = (red[0][t] + red[1][t] + red[2][t] + red[3][t]) * (1.0f / (float)S);
            for (int row = 0; row < 16; ++row) ob[(size_t)row * H + t] = tot;
        }
        return;
    }

    const int lo = max(fl - 1, 0);
    {
        const int row = t >> 4, lane = t & 15;
        const float* srow = scores + ((size_t)bh * S + (r0 + row)) * S;
        float m = -1e30f;
        for (int c = lo + lane; c < PROX; c += 16) m = fmaxf(m, srow[c]);
#pragma unroll
        for (int o = 8; o; o >>= 1) m = fmaxf(m, __shfl_xor_sync(0xffffffffu, m, o));
        float z = 0.f;
        for (int c = lo + lane; c < PROX; c += 16) {
            float e = expf(srow[c] - m);
            pt[c - lo][row] = e;
            z += e;
        }
#pragma unroll
        for (int o = 8; o; o >>= 1) z += __shfl_xor_sync(0xffffffffu, z, o);
        if (lane == 0) zrow[row] = z;
    }
    __syncthreads();

    float4 acc[16];
    if (t < 128) {
#pragma unroll
        for (int rr = 0; rr < 16; rr++) acc[rr] = make_float4(0.f, 0.f, 0.f, 0.f);
        const int dc = t & 15, g = t >> 4;
        for (int c = lo + g; c < PROX; c += 8) {
            float4 v4 = *(const float4*)(vb + (size_t)c * H + dc * 4);
            const float* pc = pt[c - lo];
#pragma unroll
            for (int rr = 0; rr < 16; rr++) {
                float p = pc[rr];
                acc[rr].x += p * v4.x; acc[rr].y += p * v4.y;
                acc[rr].z += p * v4.z; acc[rr].w += p * v4.w;
            }
        }
    }
    for (int gg = 0; gg < 8; gg++) {
        if (t < 128 && (t >> 4) == gg) {
            const int dc = t & 15;
#pragma unroll
            for (int rr = 0; rr < 16; rr++) {
                if (gg == 0) *(float4*)&red[rr][dc * 4] = acc[rr];
                else {
                    float4 cur = *(float4*)&red[rr][dc * 4];
                    cur.x += acc[rr].x; cur.y += acc[rr].y;
                    cur.z += acc[rr].z; cur.w += acc[rr].w;
                    *(float4*)&red[rr][dc * 4] = cur;
                }
            }
        }
        __syncthreads();
    }
    {
        int idx = t * 4;
        int row = idx >> 6, d = idx & 63;
        float invZ = 1.f / zrow[row];
        float4 o = make_float4(red[row][d] * invZ, red[row][d + 1] * invZ,
                               red[row][d + 2] * invZ, red[row][d + 3] * invZ);
        *(float4*)(ob + (size_t)row * H + d) = o;
    }
}

// ---------------------------------------------------------------------------
// Launch
// ---------------------------------------------------------------------------
extern "C" void kernel_launch(void* const* d_in, const int* in_sizes, int n_in,
                              void* d_out, int out_size)
{
    const float* hidden  = (const float*)d_in[0];
    const float* context = (const float*)d_in[1];
    const float* am      = (const float*)d_in[2];
    const float* gate    = (const float*)d_in[3];
    const float* vis     = (const float*)d_in[4];
    const float* Wq      = (const float*)d_in[5];
    const float* bq      = (const float*)d_in[6];
    const float* Wk      = (const float*)d_in[7];
    const float* bk      = (const float*)d_in[8];
    const float* Wv      = (const float*)d_in[9];
    const float* bv      = (const float*)d_in[10];
    const int*   feat    = (const int*)d_in[11];

    float* outp = (float*)d_out;
    float* scores;
    if ((size_t)out_size >= OUT_ELEMS + SCORES_ELEMS) {
        scores = outp + OUT_ELEMS;
    } else {
        void* p = nullptr;
        cudaGetSymbolAddress(&p, g_scores_fb);
        scores = (float*)p;
    }

    cudaFuncSetAttribute(qkv_mma_f16,  cudaFuncAttributeMaxDynamicSharedMemorySize, QKV_SMEM);
    cudaFuncSetAttribute(qkv_mma_bf16, cudaFuncAttributeMaxDynamicSharedMemorySize, QKV_SMEM);

    add_prep<<<(unsigned)(OUT_ELEMS / 4 / 256), 256>>>(hidden, context, vis, feat);
    {
        dim3 g((H * H / 4 + 255) / 256, 3);
        prep_w<<<g, 256>>>(Wq, Wk, Wv);
    }
    {
        dim3 gridQK(H / 128, M_TOT / 128, 2);
        qkv_mma_f16<<<gridQK, 256, QKV_SMEM>>>(bq, bk);
        dim3 gridV(H / 128, M_TOT / 128, 1);
        qkv_mma_bf16<<<gridV, 256, QKV_SMEM>>>(bv);
    }
    {
        dim3 gb(PROX - 1, B * NH);
        band_scores<<<gb, 256>>>(gate, am, scores);
        dim3 gf(B * NH, 4);
        fullrow_scores<<<gf, 256>>>(gate, am, scores);
        dim3 gc(S / 64, (S - PROX) / 64, B * NH);
        block_scores<<<gc, 256>>>(gate, am, feat, scores);
    }
    {
        dim3 gt(PROX, B * NH);
        out_top<<<gt, 64>>>(scores, outp);
        dim3 gbm((S - PROX) / 16, B * NH);
        out_bottom<<<gbm, 256>>>(scores, feat, outp);
    }

    (void)in_sizes; (void)n_in;
}